// round 6
// baseline (speedup 1.0000x reference)
#include <cuda_runtime.h>
#include <math.h>

#define PI_F 3.14159265358979323846f
#define HPI_F 1.57079632679489662f

#define BB 8

// ---------- static scratch ----------
// padded RGBX L0 target copies: (B,512,1024) float4
__device__ float4 g_pad0[4194304];
__device__ float4 g_pad1[4194304];
// tgt RGBX mips: L1@0 (1048576), L2@1048576 (262144), L3@1310720 (65536)
__device__ float4 g_tgtM0[1376256];
__device__ float4 g_tgtM1[1376256];
// ref planar float mips ((b*3+c),h,w): L1@0, L2@3145728, L3@3932160
__device__ float g_refM[4128768];
__device__ float g_R[BB * 2 * 9];
__device__ float g_t[BB * 2 * 3];
// sincos tables: lon sizes 1024,512,256,128 @ offs 0,1024,1536,1792
//                lat sizes 512,256,128,64  @ offs 0,512,768,896
__device__ float2 g_lonT[1920];
__device__ float2 g_latT[960];
__device__ double g_acc[4];
__device__ int g_done;

#define TOTAL_LOSS_BLOCKS (16384 + 5376)

// ---------- init ----------
__global__ void bp_init(const float* __restrict__ pose) {
    int tid = threadIdx.x;
    if (tid < 4) g_acc[tid] = 0.0;
    if (tid == 4) g_done = 0;
    if (tid < BB * 2) {
        const float* p = pose + tid * 6;
        float rx = p[3], ry = p[4], rz = p[5];
        float th = sqrtf(rx * rx + ry * ry + rz * rz);
        float inv = 1.0f / fmaxf(th, 1e-8f);
        float kx = rx * inv, ky = ry * inv, kz = rz * inv;
        float s = sinf(th), c = cosf(th), ic = 1.0f - c;
        float* R = g_R + tid * 9;
        R[0] = c + ic * kx * kx;      R[1] = ic * kx * ky - s * kz; R[2] = ic * kx * kz + s * ky;
        R[3] = ic * ky * kx + s * kz; R[4] = c + ic * ky * ky;      R[5] = ic * ky * kz - s * kx;
        R[6] = ic * kz * kx - s * ky; R[7] = ic * kz * ky + s * kx; R[8] = c + ic * kz * kz;
        float* t = g_t + tid * 3;
        t[0] = p[0]; t[1] = p[1]; t[2] = p[2];
    }
    for (int i = tid; i < 1920; i += 256) {
        int off, w;
        if (i < 1024)      { off = 0;    w = 1024; }
        else if (i < 1536) { off = 1024; w = 512; }
        else if (i < 1792) { off = 1536; w = 256; }
        else               { off = 1792; w = 128; }
        int xi = i - off;
        float lon = ((xi + 0.5f) / (float)w * 2.0f - 1.0f) * PI_F;
        g_lonT[i] = make_float2(sinf(lon), cosf(lon));
    }
    for (int i = tid; i < 960; i += 256) {
        int off, h;
        if (i < 512)      { off = 0;   h = 512; }
        else if (i < 768) { off = 512; h = 256; }
        else if (i < 896) { off = 768; h = 128; }
        else              { off = 896; h = 64; }
        int yi = i - off;
        float lat = -((yi + 0.5f) / (float)h * 2.0f - 1.0f) * HPI_F;
        g_latT[i] = make_float2(sinf(lat), cosf(lat));
    }
}

// ---------- fast atan poly on [0,1], max err ~1e-5 rad ----------
__device__ __forceinline__ float atanp(float r) {
    float z = r * r;
    float p = -0.0117212f;
    p = fmaf(p, z, 0.05265332f);
    p = fmaf(p, z, -0.11643287f);
    p = fmaf(p, z, 0.19354346f);
    p = fmaf(p, z, -0.33262347f);
    p = fmaf(p, z, 0.99997726f);
    return r * p;
}

// ---------- one warped-frame L1 term, RGBX float4 gather ----------
__device__ __forceinline__ float warp_term4(
    const float4* __restrict__ tg, int b, int h, int w,
    float px, float py, float pz,
    float r0, float r1, float r2, float m)
{
    float ax = fabsf(px), az = fabsf(pz);
    float mn = fminf(ax, az), mx = fmaxf(ax, az);
    float t = atanp(__fdividef(mn, mx));
    t = (ax > az) ? (HPI_F - t) : t;
    t = (pz < 0.0f) ? (PI_F - t) : t;
    float lo = copysignf(t, px);
    float q = py * py;
    float s2 = fmaf(px, px, pz * pz);
    float mn2 = fminf(q, s2), mx2 = fmaxf(q, s2);
    float t2 = atanp(sqrtf(__fdividef(mn2, mx2)));
    t2 = (q > s2) ? (HPI_F - t2) : t2;
    float la = copysignf(t2, py);

    float fx = (lo * (1.0f / PI_F) + 1.0f) * (0.5f * (float)(w - 1));
    float fy = (la * (2.0f / PI_F) + 1.0f) * (0.5f * (float)(h - 1));
    float x0f = floorf(fx), y0f = floorf(fy);
    float wx1 = fx - x0f, wy1 = fy - y0f;
    float wx0 = 1.0f - wx1, wy0 = 1.0f - wy1;
    int x0 = (int)x0f, y0 = (int)y0f;
    int x1 = min(x0 + 1, w - 1), y1 = min(y0 + 1, h - 1);
    x0 = max(min(x0, w - 1), 0); y0 = max(min(y0, h - 1), 0);
    x1 = max(x1, 0); y1 = max(y1, 0);
    float wa = wx0 * wy0, wb = wx0 * wy1, wc = wx1 * wy0, wd = wx1 * wy1;

    const float4* base = tg + (size_t)b * h * w;
    float4 v00 = __ldg(base + y0 * w + x0);
    float4 v01 = __ldg(base + y1 * w + x0);
    float4 v10 = __ldg(base + y0 * w + x1);
    float4 v11 = __ldg(base + y1 * w + x1);
    float w0 = wa * v00.x + wb * v01.x + wc * v10.x + wd * v11.x;
    float w1 = wa * v00.y + wb * v01.y + wc * v10.y + wd * v11.y;
    float w2 = wa * v00.z + wb * v01.z + wc * v10.z + wd * v11.z;
    return m * (fabsf(r0 - w0) + fabsf(r1 - w1) + fabsf(r2 - w2));
}

// ---------- block reduce + done-count finalize ----------
__device__ __forceinline__ void loss_reduce_finalize(float acc, int accIdx, float* out) {
    #pragma unroll
    for (int o = 16; o > 0; o >>= 1) acc += __shfl_down_sync(0xffffffffu, acc, o);
    __shared__ float ws[8];
    int lane = threadIdx.x & 31, warp = threadIdx.x >> 5;
    if (lane == 0) ws[warp] = acc;
    __syncthreads();
    if (threadIdx.x == 0) {
        float s = 0.0f;
        #pragma unroll
        for (int i = 0; i < 8; i++) s += ws[i];
        atomicAdd(&g_acc[accIdx], (double)s);
        __threadfence();
        int done = atomicAdd(&g_done, 1);
        if (done == TOTAL_LOSS_BLOCKS - 1) {
            double l = g_acc[0] * (1.0 / 12582912.0)
                     + g_acc[1] * (1.0 / 3145728.0)
                     + g_acc[2] * (1.0 / 786432.0)
                     + g_acc[3] * (1.0 / 196608.0);
            out[0] = (float)l;
        }
    }
}

// ---------- DENSE pass: padded L0 tgt copies + full mip pyramid in-block ----------
// Block = 16x16 pixel tile; warp = 16x2 rows. L1 via shfl, L2/L3 via smem.
__global__ __launch_bounds__(256) void bp_dense(
    const float* __restrict__ ref, const float* __restrict__ tgt0,
    const float* __restrict__ tgt1)
{
    int tid = threadIdx.x;
    int lane = tid & 31, wid = tid >> 5;
    int blk = blockIdx.x;            // 16384 = 64 x 32 x 8
    int bx = blk & 63;
    int by = (blk >> 6) & 31;
    int b  = blk >> 11;
    int tx = lane & 15;
    int sub = lane >> 4;
    int x = bx * 16 + tx;
    int y = by * 16 + wid * 2 + sub;

    const int hw = 512 * 1024;
    int p = y * 1024 + x;
    size_t base3 = (size_t)b * 3 * hw + p;

    float r0 = __ldg(ref + base3), r1 = __ldg(ref + base3 + hw), r2 = __ldg(ref + base3 + 2 * hw);
    float t00 = __ldg(tgt0 + base3), t01 = __ldg(tgt0 + base3 + hw), t02 = __ldg(tgt0 + base3 + 2 * hw);
    float t10 = __ldg(tgt1 + base3), t11 = __ldg(tgt1 + base3 + hw), t12 = __ldg(tgt1 + base3 + 2 * hw);

    int padIdx = (b * 512 + y) * 1024 + x;
    g_pad0[padIdx] = make_float4(t00, t01, t02, 0.0f);
    g_pad1[padIdx] = make_float4(t10, t11, t12, 0.0f);

    // ---- L1 (2x2) via shuffles ----
    #define RED4(v) { v += __shfl_xor_sync(0xffffffffu, v, 1); v += __shfl_xor_sync(0xffffffffu, v, 16); v *= 0.25f; }
    float a0 = r0, a1 = r1, a2 = r2;
    float c00 = t00, c01 = t01, c02 = t02;
    float c10 = t10, c11 = t11, c12 = t12;
    RED4(a0); RED4(a1); RED4(a2);
    RED4(c00); RED4(c01); RED4(c02);
    RED4(c10); RED4(c11); RED4(c12);
    #undef RED4

    __shared__ float  sref[3][64];
    __shared__ float4 st0[64];
    __shared__ float4 st1[64];
    __shared__ float  sref2[3][16];
    __shared__ float4 st0b[16];
    __shared__ float4 st1b[16];

    if (sub == 0 && (tx & 1) == 0) {
        int lx = tx >> 1, ly = wid;              // 8x8 local L1
        int x2 = bx * 8 + lx, y2 = by * 8 + ly;
        size_t ro = (size_t)b * 393216 + y2 * 512 + x2;
        g_refM[ro] = a0; g_refM[ro + 131072] = a1; g_refM[ro + 262144] = a2;
        float4 v0 = make_float4(c00, c01, c02, 0.0f);
        float4 v1 = make_float4(c10, c11, c12, 0.0f);
        g_tgtM0[(b * 256 + y2) * 512 + x2] = v0;
        g_tgtM1[(b * 256 + y2) * 512 + x2] = v1;
        int si = ly * 8 + lx;
        sref[0][si] = a0; sref[1][si] = a1; sref[2][si] = a2;
        st0[si] = v0; st1[si] = v1;
    }
    __syncthreads();

    // ---- L2 (4x4 per block) ----
    if (tid < 16) {
        int lx2 = tid & 3, ly2 = tid >> 2;
        int i00 = (2 * ly2) * 8 + 2 * lx2;
        int i01 = i00 + 1, i10 = i00 + 8, i11 = i00 + 9;
        float e0 = 0.25f * (sref[0][i00] + sref[0][i01] + sref[0][i10] + sref[0][i11]);
        float e1 = 0.25f * (sref[1][i00] + sref[1][i01] + sref[1][i10] + sref[1][i11]);
        float e2 = 0.25f * (sref[2][i00] + sref[2][i01] + sref[2][i10] + sref[2][i11]);
        float4 q0 = make_float4(
            0.25f * (st0[i00].x + st0[i01].x + st0[i10].x + st0[i11].x),
            0.25f * (st0[i00].y + st0[i01].y + st0[i10].y + st0[i11].y),
            0.25f * (st0[i00].z + st0[i01].z + st0[i10].z + st0[i11].z), 0.0f);
        float4 q1 = make_float4(
            0.25f * (st1[i00].x + st1[i01].x + st1[i10].x + st1[i11].x),
            0.25f * (st1[i00].y + st1[i01].y + st1[i10].y + st1[i11].y),
            0.25f * (st1[i00].z + st1[i01].z + st1[i10].z + st1[i11].z), 0.0f);
        int x2g = bx * 4 + lx2, y2g = by * 4 + ly2;
        size_t r2b = 3145728 + (size_t)b * 98304 + y2g * 256 + x2g;
        g_refM[r2b] = e0; g_refM[r2b + 32768] = e1; g_refM[r2b + 65536] = e2;
        g_tgtM0[1048576 + (b * 128 + y2g) * 256 + x2g] = q0;
        g_tgtM1[1048576 + (b * 128 + y2g) * 256 + x2g] = q1;
        int si = ly2 * 4 + lx2;
        sref2[0][si] = e0; sref2[1][si] = e1; sref2[2][si] = e2;
        st0b[si] = q0; st1b[si] = q1;
    }
    __syncthreads();

    // ---- L3 (2x2 per block) ----
    if (tid < 4) {
        int lx3 = tid & 1, ly3 = tid >> 1;
        int i00 = (2 * ly3) * 4 + 2 * lx3;
        int i01 = i00 + 1, i10 = i00 + 4, i11 = i00 + 5;
        float e0 = 0.25f * (sref2[0][i00] + sref2[0][i01] + sref2[0][i10] + sref2[0][i11]);
        float e1 = 0.25f * (sref2[1][i00] + sref2[1][i01] + sref2[1][i10] + sref2[1][i11]);
        float e2 = 0.25f * (sref2[2][i00] + sref2[2][i01] + sref2[2][i10] + sref2[2][i11]);
        float4 q0 = make_float4(
            0.25f * (st0b[i00].x + st0b[i01].x + st0b[i10].x + st0b[i11].x),
            0.25f * (st0b[i00].y + st0b[i01].y + st0b[i10].y + st0b[i11].y),
            0.25f * (st0b[i00].z + st0b[i01].z + st0b[i10].z + st0b[i11].z), 0.0f);
        float4 q1 = make_float4(
            0.25f * (st1b[i00].x + st1b[i01].x + st1b[i10].x + st1b[i11].x),
            0.25f * (st1b[i00].y + st1b[i01].y + st1b[i10].y + st1b[i11].y),
            0.25f * (st1b[i00].z + st1b[i01].z + st1b[i10].z + st1b[i11].z), 0.0f);
        int x3g = bx * 2 + lx3, y3g = by * 2 + ly3;
        size_t r3b = 3932160 + (size_t)b * 24576 + y3g * 128 + x3g;
        g_refM[r3b] = e0; g_refM[r3b + 8192] = e1; g_refM[r3b + 16384] = e2;
        g_tgtM0[1310720 + (b * 64 + y3g) * 128 + x3g] = q0;
        g_tgtM1[1310720 + (b * 64 + y3g) * 128 + x3g] = q1;
    }
}

// ---------- loss level 0: dense reads + RGBX gathers from padded copies ----------
__global__ __launch_bounds__(256) void bp_loss0(
    const float* __restrict__ ref, const float* __restrict__ depth,
    const float* __restrict__ mask, float* __restrict__ out)
{
    int idx = blockIdx.x * 256 + threadIdx.x;
    int x = idx & 1023, y = (idx >> 10) & 511, b = idx >> 19;
    const int hw = 512 * 1024;
    int p = y * 1024 + x;
    size_t base3 = (size_t)b * 3 * hw + p;
    float r0 = __ldg(ref + base3), r1 = __ldg(ref + base3 + hw), r2 = __ldg(ref + base3 + 2 * hw);
    float d  = __ldg(depth + (size_t)b * hw + p);
    float m0 = __ldg(mask + (size_t)(b * 2) * hw + p);
    float m1 = __ldg(mask + (size_t)(b * 2 + 1) * hw + p);

    float2 lc = g_lonT[x];
    float2 lt = g_latT[y];
    float xx = d * lt.y * lc.x;
    float yy = d * lt.x;
    float zz = d * lt.y * lc.y;
    float acc = 0.0f;
    #pragma unroll
    for (int n = 0; n < 2; n++) {
        const float* Rm = g_R + (b * 2 + n) * 9;
        const float* tv = g_t + (b * 2 + n) * 3;
        float px = __ldg(Rm+0) * xx + __ldg(Rm+1) * yy + __ldg(Rm+2) * zz + __ldg(tv+0);
        float py = __ldg(Rm+3) * xx + __ldg(Rm+4) * yy + __ldg(Rm+5) * zz + __ldg(tv+1);
        float pz = __ldg(Rm+6) * xx + __ldg(Rm+7) * yy + __ldg(Rm+8) * zz + __ldg(tv+2);
        acc += warp_term4(n ? g_pad1 : g_pad0, b, 512, 1024, px, py, pz, r0, r1, r2, n ? m1 : m0);
    }
    loss_reduce_finalize(acc, 0, out);
}

// ---------- loss levels 1..3 merged ----------
__global__ __launch_bounds__(256) void bp_loss123(
    const float* __restrict__ d1, const float* __restrict__ m1,
    const float* __restrict__ d2, const float* __restrict__ m2,
    const float* __restrict__ d3, const float* __restrict__ m3,
    float* __restrict__ out)
{
    int blk = blockIdx.x;
    const float *dep, *msk;
    int h, w, lw, lh, lonO, latO, accI, base;
    int toff; size_t roff;
    if (blk < 4096)      { dep = d1; msk = m1; h = 256; w = 512; lw = 9; lh = 8; lonO = 1024; latO = 512; toff = 0;       roff = 0;       accI = 1; base = 0; }
    else if (blk < 5120) { dep = d2; msk = m2; h = 128; w = 256; lw = 8; lh = 7; lonO = 1536; latO = 768; toff = 1048576; roff = 3145728; accI = 2; base = 4096; }
    else                 { dep = d3; msk = m3; h = 64;  w = 128; lw = 7; lh = 6; lonO = 1792; latO = 896; toff = 1310720; roff = 3932160; accI = 3; base = 5120; }
    int idx = (blk - base) * 256 + threadIdx.x;
    int x = idx & (w - 1), y = (idx >> lw) & (h - 1), b = idx >> (lw + lh);
    float2 lc = g_lonT[lonO + x];
    float2 lt = g_latT[latO + y];
    float d = __ldg(dep + idx);
    float xx = d * lt.y * lc.x;
    float yy = d * lt.x;
    float zz = d * lt.y * lc.y;
    int hw = h * w;
    int p = y * w + x;
    const float* rp = g_refM + roff + (size_t)b * 3 * hw + p;
    float r0 = rp[0], r1 = rp[hw], r2 = rp[2 * hw];
    float acc = 0.0f;
    #pragma unroll
    for (int n = 0; n < 2; n++) {
        const float* Rm = g_R + (b * 2 + n) * 9;
        const float* tv = g_t + (b * 2 + n) * 3;
        float px = __ldg(Rm+0) * xx + __ldg(Rm+1) * yy + __ldg(Rm+2) * zz + __ldg(tv+0);
        float py = __ldg(Rm+3) * xx + __ldg(Rm+4) * yy + __ldg(Rm+5) * zz + __ldg(tv+1);
        float pz = __ldg(Rm+6) * xx + __ldg(Rm+7) * yy + __ldg(Rm+8) * zz + __ldg(tv+2);
        float m = __ldg(msk + (size_t)(b * 2 + n) * hw + p);
        acc += warp_term4((n ? g_tgtM1 : g_tgtM0) + toff, b, h, w, px, py, pz, r0, r1, r2, m);
    }
    loss_reduce_finalize(acc, accI, out);
}

extern "C" void kernel_launch(void* const* d_in, const int* in_sizes, int n_in,
                              void* d_out, int out_size) {
    const float* depth[4];
    const float* mask[4];
    // Input-order detection: interleaved (dict order) vs grouped (signature order).
    if (in_sizes[2] == 8388608) {
        for (int i = 0; i < 4; i++) {
            depth[i] = (const float*)d_in[1 + 2 * i];
            mask[i]  = (const float*)d_in[2 + 2 * i];
        }
    } else {
        for (int i = 0; i < 4; i++) {
            depth[i] = (const float*)d_in[1 + i];
            mask[i]  = (const float*)d_in[5 + i];
        }
    }
    const float* ref_rgb = (const float*)d_in[0];
    const float* tgt0 = (const float*)d_in[9];
    const float* tgt1 = (const float*)d_in[10];
    const float* pose = (const float*)d_in[11];
    float* out = (float*)d_out;

    bp_init<<<1, 256>>>(pose);
    bp_dense<<<16384, 256>>>(ref_rgb, tgt0, tgt1);
    bp_loss0<<<16384, 256>>>(ref_rgb, depth[0], mask[0], out);
    bp_loss123<<<5376, 256>>>(depth[1], mask[1], depth[2], mask[2], depth[3], mask[3], out);
    (void)n_in; (void)out_size;
}

// round 8
// speedup vs baseline: 1.1379x; 1.1379x over previous
#include <cuda_runtime.h>
#include <math.h>

#define PI_F 3.14159265358979323846f
#define HPI_F 1.57079632679489662f

#define BB 8

// ---------- static scratch ----------
// L0 quad arrays: entry (b,y,x) = 4 corners (8-bit RGB each) of bilinear at (x..x+1, y..y+1)
__device__ uint4 g_q0[BB * 512 * 1024];   // 67MB
__device__ uint4 g_q1[BB * 512 * 1024];
// linear packed-RGB8 tgt mips per frame: L1@0 (1048576), L2@1048576 (262144), L3@1310720 (65536)
__device__ unsigned int g_c0[1376256];
__device__ unsigned int g_c1[1376256];
// quad mips (same offsets)
__device__ uint4 g_qm0[1376256];
__device__ uint4 g_qm1[1376256];
// ref planar fp32 mips ((b*3+c),h,w): L1@0, L2@3145728, L3@3932160
__device__ float g_refM[4128768];
__device__ float g_R[BB * 2 * 9];
__device__ float g_t[BB * 2 * 3];
// sincos tables: lon sizes 1024,512,256,128 @ offs 0,1024,1536,1792
//                lat sizes 512,256,128,64  @ offs 0,512,768,896
__device__ float2 g_lonT[1920];
__device__ float2 g_latT[960];
__device__ double g_acc[4];
__device__ int g_done;

#define TOTAL_LOSS_BLOCKS (16384 + 5376)

// ---------- init ----------
__global__ void bp_init(const float* __restrict__ pose) {
    int tid = threadIdx.x;
    if (tid < 4) g_acc[tid] = 0.0;
    if (tid == 4) g_done = 0;
    if (tid < BB * 2) {
        const float* p = pose + tid * 6;
        float rx = p[3], ry = p[4], rz = p[5];
        float th = sqrtf(rx * rx + ry * ry + rz * rz);
        float inv = 1.0f / fmaxf(th, 1e-8f);
        float kx = rx * inv, ky = ry * inv, kz = rz * inv;
        float s = sinf(th), c = cosf(th), ic = 1.0f - c;
        float* R = g_R + tid * 9;
        R[0] = c + ic * kx * kx;      R[1] = ic * kx * ky - s * kz; R[2] = ic * kx * kz + s * ky;
        R[3] = ic * ky * kx + s * kz; R[4] = c + ic * ky * ky;      R[5] = ic * ky * kz - s * kx;
        R[6] = ic * kz * kx - s * ky; R[7] = ic * kz * ky + s * kx; R[8] = c + ic * kz * kz;
        float* t = g_t + tid * 3;
        t[0] = p[0]; t[1] = p[1]; t[2] = p[2];
    }
    for (int i = tid; i < 1920; i += 256) {
        int off, w;
        if (i < 1024)      { off = 0;    w = 1024; }
        else if (i < 1536) { off = 1024; w = 512; }
        else if (i < 1792) { off = 1536; w = 256; }
        else               { off = 1792; w = 128; }
        int xi = i - off;
        float lon = ((xi + 0.5f) / (float)w * 2.0f - 1.0f) * PI_F;
        g_lonT[i] = make_float2(sinf(lon), cosf(lon));
    }
    for (int i = tid; i < 960; i += 256) {
        int off, h;
        if (i < 512)      { off = 0;   h = 512; }
        else if (i < 768) { off = 512; h = 256; }
        else if (i < 896) { off = 768; h = 128; }
        else              { off = 896; h = 64; }
        int yi = i - off;
        float lat = -((yi + 0.5f) / (float)h * 2.0f - 1.0f) * HPI_F;
        g_latT[i] = make_float2(sinf(lat), cosf(lat));
    }
}

// ---------- fast atan poly on [0,1], max err ~1e-5 rad ----------
__device__ __forceinline__ float atanp(float r) {
    float z = r * r;
    float p = -0.0117212f;
    p = fmaf(p, z, 0.05265332f);
    p = fmaf(p, z, -0.11643287f);
    p = fmaf(p, z, 0.19354346f);
    p = fmaf(p, z, -0.33262347f);
    p = fmaf(p, z, 0.99997726f);
    return r * p;
}

// ---------- project -> clamped sample coords ----------
__device__ __forceinline__ void project_eq(
    float px, float py, float pz, int h, int w, float& fx, float& fy)
{
    float ax = fabsf(px), az = fabsf(pz);
    float mn = fminf(ax, az), mx = fmaxf(ax, az);
    float t = atanp(__fdividef(mn, mx));
    t = (ax > az) ? (HPI_F - t) : t;
    t = (pz < 0.0f) ? (PI_F - t) : t;
    float lo = copysignf(t, px);
    float q = py * py;
    float s2 = fmaf(px, px, pz * pz);
    float mn2 = fminf(q, s2), mx2 = fmaxf(q, s2);
    float t2 = atanp(sqrtf(__fdividef(mn2, mx2)));
    t2 = (q > s2) ? (HPI_F - t2) : t2;
    float la = copysignf(t2, py);
    fx = (lo * (1.0f / PI_F) + 1.0f) * (0.5f * (float)(w - 1));
    fy = (la * (2.0f / PI_F) + 1.0f) * (0.5f * (float)(h - 1));
    fx = fminf(fmaxf(fx, 0.0f), (float)(w - 1));
    fy = fminf(fmaxf(fy, 0.0f), (float)(h - 1));
}

// ---------- quantize 3 fp32 -> packed RGB8 ----------
__device__ __forceinline__ unsigned int q8(float a, float b, float c) {
    unsigned int r = __float2uint_rn(__saturatef(a) * 255.0f);
    unsigned int g = __float2uint_rn(__saturatef(b) * 255.0f);
    unsigned int bl = __float2uint_rn(__saturatef(c) * 255.0f);
    return r | (g << 8) | (bl << 16);
}

#define BF(u, k) ((float)(((u) >> (k)) & 0xffu))

// ---------- quad bilinear loss term ----------
// Q.x=(y0,x0) Q.y=(y0,x1) Q.z=(y1,x0) Q.w=(y1,x1)
__device__ __forceinline__ float quad_term(
    const uint4* __restrict__ Qarr, int b, int h, int w,
    float fx, float fy, float r0, float r1, float r2, float m)
{
    float x0f = floorf(fx), y0f = floorf(fy);
    int x0 = (int)x0f, y0 = (int)y0f;
    float wx1 = fx - x0f, wy1 = fy - y0f;
    float wx0 = 1.0f - wx1, wy0 = 1.0f - wy1;
    float wa = wx0 * wy0, wc = wx1 * wy0, wb = wx0 * wy1, wd = wx1 * wy1;
    uint4 Q = __ldg(Qarr + (size_t)(b * h + y0) * w + x0);
    float w0 = (wa * BF(Q.x, 0)  + wc * BF(Q.y, 0)  + wb * BF(Q.z, 0)  + wd * BF(Q.w, 0))  * (1.0f / 255.0f);
    float w1 = (wa * BF(Q.x, 8)  + wc * BF(Q.y, 8)  + wb * BF(Q.z, 8)  + wd * BF(Q.w, 8))  * (1.0f / 255.0f);
    float w2 = (wa * BF(Q.x, 16) + wc * BF(Q.y, 16) + wb * BF(Q.z, 16) + wd * BF(Q.w, 16)) * (1.0f / 255.0f);
    return m * (fabsf(r0 - w0) + fabsf(r1 - w1) + fabsf(r2 - w2));
}

// ---------- block reduce + done-count finalize ----------
__device__ __forceinline__ void loss_reduce_finalize(float acc, int accIdx, float* out) {
    #pragma unroll
    for (int o = 16; o > 0; o >>= 1) acc += __shfl_down_sync(0xffffffffu, acc, o);
    __shared__ float ws[8];
    int lane = threadIdx.x & 31, warp = threadIdx.x >> 5;
    if (lane == 0) ws[warp] = acc;
    __syncthreads();
    if (threadIdx.x == 0) {
        float s = 0.0f;
        #pragma unroll
        for (int i = 0; i < 8; i++) s += ws[i];
        atomicAdd(&g_acc[accIdx], (double)s);
        __threadfence();
        int done = atomicAdd(&g_done, 1);
        if (done == TOTAL_LOSS_BLOCKS - 1) {
            double l = g_acc[0] * (1.0 / 12582912.0)
                     + g_acc[1] * (1.0 / 3145728.0)
                     + g_acc[2] * (1.0 / 786432.0)
                     + g_acc[3] * (1.0 / 196608.0);
            out[0] = (float)l;
        }
    }
}

// ---------- DENSE: L0 quads + fp32 ref mips + RGB8 tgt mips ----------
// Block = 16x16 pixel tile; warp = 16x2 rows (lane = tx + 16*sub).
__global__ __launch_bounds__(256) void bp_dense(
    const float* __restrict__ ref, const float* __restrict__ tgt0,
    const float* __restrict__ tgt1)
{
    int tid = threadIdx.x;
    int lane = tid & 31, wid = tid >> 5;
    int blk = blockIdx.x;            // 16384 = 64 x 32 x 8
    int bx = blk & 63;
    int by = (blk >> 6) & 31;
    int b  = blk >> 11;
    int tx = lane & 15;
    int sub = lane >> 4;
    int lx = tx, ly = wid * 2 + sub;
    int x = bx * 16 + lx;
    int y = by * 16 + ly;

    const int hw = 512 * 1024;
    int p = y * 1024 + x;
    size_t base3 = (size_t)b * 3 * hw + p;

    float r0 = __ldg(ref + base3), r1 = __ldg(ref + base3 + hw), r2 = __ldg(ref + base3 + 2 * hw);
    float t00 = __ldg(tgt0 + base3), t01 = __ldg(tgt0 + base3 + hw), t02 = __ldg(tgt0 + base3 + 2 * hw);
    float t10 = __ldg(tgt1 + base3), t11 = __ldg(tgt1 + base3 + hw), t12 = __ldg(tgt1 + base3 + 2 * hw);

    __shared__ unsigned int sm0[17 * 17], sm1[17 * 17];
    sm0[ly * 17 + lx] = q8(t00, t01, t02);
    sm1[ly * 17 + lx] = q8(t10, t11, t12);
    // halo: right column (17) + bottom row (16)
    if (tid < 33) {
        int hlx, hly;
        if (tid < 17) { hlx = 16; hly = tid; }
        else          { hlx = tid - 17; hly = 16; }
        int gx = min(bx * 16 + hlx, 1023);
        int gy = min(by * 16 + hly, 511);
        size_t hb = (size_t)b * 3 * hw + gy * 1024 + gx;
        sm0[hly * 17 + hlx] = q8(__ldg(tgt0 + hb), __ldg(tgt0 + hb + hw), __ldg(tgt0 + hb + 2 * hw));
        sm1[hly * 17 + hlx] = q8(__ldg(tgt1 + hb), __ldg(tgt1 + hb + hw), __ldg(tgt1 + hb + 2 * hw));
    }

    // ---- L1 (2x2) via shuffles (fp32) ----
    #define RED4(v) { v += __shfl_xor_sync(0xffffffffu, v, 1); v += __shfl_xor_sync(0xffffffffu, v, 16); v *= 0.25f; }
    float a0 = r0, a1 = r1, a2 = r2;
    float c00 = t00, c01 = t01, c02 = t02;
    float c10 = t10, c11 = t11, c12 = t12;
    RED4(a0); RED4(a1); RED4(a2);
    RED4(c00); RED4(c01); RED4(c02);
    RED4(c10); RED4(c11); RED4(c12);
    #undef RED4

    __shared__ float  sref[3][64];
    __shared__ float4 st0[64];
    __shared__ float4 st1[64];
    __shared__ float  sref2[3][16];
    __shared__ float4 st0b[16];
    __shared__ float4 st1b[16];

    if (sub == 0 && (tx & 1) == 0) {
        int llx = tx >> 1, lly = wid;            // 8x8 local L1
        int x2 = bx * 8 + llx, y2 = by * 8 + lly;
        size_t ro = (size_t)b * 393216 + y2 * 512 + x2;
        g_refM[ro] = a0; g_refM[ro + 131072] = a1; g_refM[ro + 262144] = a2;
        g_c0[(b * 256 + y2) * 512 + x2] = q8(c00, c01, c02);
        g_c1[(b * 256 + y2) * 512 + x2] = q8(c10, c11, c12);
        int si = lly * 8 + llx;
        sref[0][si] = a0; sref[1][si] = a1; sref[2][si] = a2;
        st0[si] = make_float4(c00, c01, c02, 0.0f);
        st1[si] = make_float4(c10, c11, c12, 0.0f);
    }
    __syncthreads();

    // ---- L0 quad assembly + write ----
    {
        int si = ly * 17 + lx;
        uint4 q0 = make_uint4(sm0[si], sm0[si + 1], sm0[si + 17], sm0[si + 18]);
        uint4 q1 = make_uint4(sm1[si], sm1[si + 1], sm1[si + 17], sm1[si + 18]);
        g_q0[(size_t)(b * 512 + y) * 1024 + x] = q0;
        g_q1[(size_t)(b * 512 + y) * 1024 + x] = q1;
    }

    // ---- L2 (4x4 per block) ----
    if (tid < 16) {
        int lx2 = tid & 3, ly2 = tid >> 2;
        int i00 = (2 * ly2) * 8 + 2 * lx2;
        int i01 = i00 + 1, i10 = i00 + 8, i11 = i00 + 9;
        float e0 = 0.25f * (sref[0][i00] + sref[0][i01] + sref[0][i10] + sref[0][i11]);
        float e1 = 0.25f * (sref[1][i00] + sref[1][i01] + sref[1][i10] + sref[1][i11]);
        float e2 = 0.25f * (sref[2][i00] + sref[2][i01] + sref[2][i10] + sref[2][i11]);
        float q0x = 0.25f * (st0[i00].x + st0[i01].x + st0[i10].x + st0[i11].x);
        float q0y = 0.25f * (st0[i00].y + st0[i01].y + st0[i10].y + st0[i11].y);
        float q0z = 0.25f * (st0[i00].z + st0[i01].z + st0[i10].z + st0[i11].z);
        float q1x = 0.25f * (st1[i00].x + st1[i01].x + st1[i10].x + st1[i11].x);
        float q1y = 0.25f * (st1[i00].y + st1[i01].y + st1[i10].y + st1[i11].y);
        float q1z = 0.25f * (st1[i00].z + st1[i01].z + st1[i10].z + st1[i11].z);
        int x2g = bx * 4 + lx2, y2g = by * 4 + ly2;
        size_t r2b = 3145728 + (size_t)b * 98304 + y2g * 256 + x2g;
        g_refM[r2b] = e0; g_refM[r2b + 32768] = e1; g_refM[r2b + 65536] = e2;
        g_c0[1048576 + (b * 128 + y2g) * 256 + x2g] = q8(q0x, q0y, q0z);
        g_c1[1048576 + (b * 128 + y2g) * 256 + x2g] = q8(q1x, q1y, q1z);
        int si = ly2 * 4 + lx2;
        sref2[0][si] = e0; sref2[1][si] = e1; sref2[2][si] = e2;
        st0b[si] = make_float4(q0x, q0y, q0z, 0.0f);
        st1b[si] = make_float4(q1x, q1y, q1z, 0.0f);
    }
    __syncthreads();

    // ---- L3 (2x2 per block) ----
    if (tid < 4) {
        int lx3 = tid & 1, ly3 = tid >> 1;
        int i00 = (2 * ly3) * 4 + 2 * lx3;
        int i01 = i00 + 1, i10 = i00 + 4, i11 = i00 + 5;
        float e0 = 0.25f * (sref2[0][i00] + sref2[0][i01] + sref2[0][i10] + sref2[0][i11]);
        float e1 = 0.25f * (sref2[1][i00] + sref2[1][i01] + sref2[1][i10] + sref2[1][i11]);
        float e2 = 0.25f * (sref2[2][i00] + sref2[2][i01] + sref2[2][i10] + sref2[2][i11]);
        float q0x = 0.25f * (st0b[i00].x + st0b[i01].x + st0b[i10].x + st0b[i11].x);
        float q0y = 0.25f * (st0b[i00].y + st0b[i01].y + st0b[i10].y + st0b[i11].y);
        float q0z = 0.25f * (st0b[i00].z + st0b[i01].z + st0b[i10].z + st0b[i11].z);
        float q1x = 0.25f * (st1b[i00].x + st1b[i01].x + st1b[i10].x + st1b[i11].x);
        float q1y = 0.25f * (st1b[i00].y + st1b[i01].y + st1b[i10].y + st1b[i11].y);
        float q1z = 0.25f * (st1b[i00].z + st1b[i01].z + st1b[i10].z + st1b[i11].z);
        int x3g = bx * 2 + lx3, y3g = by * 2 + ly3;
        size_t r3b = 3932160 + (size_t)b * 24576 + y3g * 128 + x3g;
        g_refM[r3b] = e0; g_refM[r3b + 8192] = e1; g_refM[r3b + 16384] = e2;
        g_c0[1310720 + (b * 64 + y3g) * 128 + x3g] = q8(q0x, q0y, q0z);
        g_c1[1310720 + (b * 64 + y3g) * 128 + x3g] = q8(q1x, q1y, q1z);
    }
}

// ---------- pack mips into quads ----------
__global__ __launch_bounds__(256) void bp_pack() {
    int i = blockIdx.x * 256 + threadIdx.x;        // [0, 2752512)
    int f = (i >= 1376256);
    int j = i - f * 1376256;
    const unsigned int* src = f ? g_c1 : g_c0;
    uint4* dst = f ? g_qm1 : g_qm0;
    int off, w, h, lw, lh;
    if (j < 1048576)      { off = 0;       w = 512; h = 256; lw = 9; lh = 8; }
    else if (j < 1310720) { off = 1048576; w = 256; h = 128; lw = 8; lh = 7; }
    else                  { off = 1310720; w = 128; h = 64;  lw = 7; lh = 6; }
    int k = j - off;
    int x = k & (w - 1), y = (k >> lw) & (h - 1), b = k >> (lw + lh);
    int xq = min(x + 1, w - 1), yq = min(y + 1, h - 1);
    int row0 = off + (b * h + y) * w;
    int row1 = off + (b * h + yq) * w;
    dst[j] = make_uint4(src[row0 + x], src[row0 + xq], src[row1 + x], src[row1 + xq]);
}

// ---------- loss level 0 ----------
__global__ __launch_bounds__(256) void bp_loss0(
    const float* __restrict__ ref, const float* __restrict__ depth,
    const float* __restrict__ mask, float* __restrict__ out)
{
    int idx = blockIdx.x * 256 + threadIdx.x;
    int x = idx & 1023, y = (idx >> 10) & 511, b = idx >> 19;
    const int hw = 512 * 1024;
    int p = y * 1024 + x;
    size_t base3 = (size_t)b * 3 * hw + p;
    float r0 = __ldg(ref + base3), r1 = __ldg(ref + base3 + hw), r2 = __ldg(ref + base3 + 2 * hw);
    float d  = __ldg(depth + (size_t)b * hw + p);
    float m0 = __ldg(mask + (size_t)(b * 2) * hw + p);
    float m1 = __ldg(mask + (size_t)(b * 2 + 1) * hw + p);

    float2 lc = g_lonT[x];
    float2 lt = g_latT[y];
    float xx = d * lt.y * lc.x;
    float yy = d * lt.x;
    float zz = d * lt.y * lc.y;
    float acc = 0.0f;
    #pragma unroll
    for (int n = 0; n < 2; n++) {
        const float* Rm = g_R + (b * 2 + n) * 9;
        const float* tv = g_t + (b * 2 + n) * 3;
        float px = __ldg(Rm+0) * xx + __ldg(Rm+1) * yy + __ldg(Rm+2) * zz + __ldg(tv+0);
        float py = __ldg(Rm+3) * xx + __ldg(Rm+4) * yy + __ldg(Rm+5) * zz + __ldg(tv+1);
        float pz = __ldg(Rm+6) * xx + __ldg(Rm+7) * yy + __ldg(Rm+8) * zz + __ldg(tv+2);
        float fx, fy;
        project_eq(px, py, pz, 512, 1024, fx, fy);
        acc += quad_term(n ? g_q1 : g_q0, b, 512, 1024, fx, fy, r0, r1, r2, n ? m1 : m0);
    }
    loss_reduce_finalize(acc, 0, out);
}

// ---------- loss levels 1..3 merged ----------
__global__ __launch_bounds__(256) void bp_loss123(
    const float* __restrict__ d1, const float* __restrict__ m1,
    const float* __restrict__ d2, const float* __restrict__ m2,
    const float* __restrict__ d3, const float* __restrict__ m3,
    float* __restrict__ out)
{
    int blk = blockIdx.x;
    const float *dep, *msk;
    int h, w, lw, lh, lonO, latO, accI, base;
    int qoff; size_t roff;
    if (blk < 4096)      { dep = d1; msk = m1; h = 256; w = 512; lw = 9; lh = 8; lonO = 1024; latO = 512; qoff = 0;       roff = 0;       accI = 1; base = 0; }
    else if (blk < 5120) { dep = d2; msk = m2; h = 128; w = 256; lw = 8; lh = 7; lonO = 1536; latO = 768; qoff = 1048576; roff = 3145728; accI = 2; base = 4096; }
    else                 { dep = d3; msk = m3; h = 64;  w = 128; lw = 7; lh = 6; lonO = 1792; latO = 896; qoff = 1310720; roff = 3932160; accI = 3; base = 5120; }
    int idx = (blk - base) * 256 + threadIdx.x;
    int x = idx & (w - 1), y = (idx >> lw) & (h - 1), b = idx >> (lw + lh);
    float2 lc = g_lonT[lonO + x];
    float2 lt = g_latT[latO + y];
    float d = __ldg(dep + idx);
    float xx = d * lt.y * lc.x;
    float yy = d * lt.x;
    float zz = d * lt.y * lc.y;
    int hw = h * w;
    int p = y * w + x;
    const float* rp = g_refM + roff + (size_t)b * 3 * hw + p;
    float r0 = rp[0], r1 = rp[hw], r2 = rp[2 * hw];
    float acc = 0.0f;
    #pragma unroll
    for (int n = 0; n < 2; n++) {
        const float* Rm = g_R + (b * 2 + n) * 9;
        const float* tv = g_t + (b * 2 + n) * 3;
        float px = __ldg(Rm+0) * xx + __ldg(Rm+1) * yy + __ldg(Rm+2) * zz + __ldg(tv+0);
        float py = __ldg(Rm+3) * xx + __ldg(Rm+4) * yy + __ldg(Rm+5) * zz + __ldg(tv+1);
        float pz = __ldg(Rm+6) * xx + __ldg(Rm+7) * yy + __ldg(Rm+8) * zz + __ldg(tv+2);
        float fx, fy;
        project_eq(px, py, pz, h, w, fx, fy);
        float m = __ldg(msk + (size_t)(b * 2 + n) * hw + p);
        acc += quad_term((n ? g_qm1 : g_qm0) + qoff, b, h, w, fx, fy, r0, r1, r2, m);
    }
    loss_reduce_finalize(acc, accI, out);
}

extern "C" void kernel_launch(void* const* d_in, const int* in_sizes, int n_in,
                              void* d_out, int out_size) {
    const float* depth[4];
    const float* mask[4];
    // Input-order detection: interleaved (dict order) vs grouped (signature order).
    if (in_sizes[2] == 8388608) {
        for (int i = 0; i < 4; i++) {
            depth[i] = (const float*)d_in[1 + 2 * i];
            mask[i]  = (const float*)d_in[2 + 2 * i];
        }
    } else {
        for (int i = 0; i < 4; i++) {
            depth[i] = (const float*)d_in[1 + i];
            mask[i]  = (const float*)d_in[5 + i];
        }
    }
    const float* ref_rgb = (const float*)d_in[0];
    const float* tgt0 = (const float*)d_in[9];
    const float* tgt1 = (const float*)d_in[10];
    const float* pose = (const float*)d_in[11];
    float* out = (float*)d_out;

    bp_init<<<1, 256>>>(pose);
    bp_dense<<<16384, 256>>>(ref_rgb, tgt0, tgt1);
    bp_pack<<<10752, 256>>>();
    bp_loss0<<<16384, 256>>>(ref_rgb, depth[0], mask[0], out);
    bp_loss123<<<5376, 256>>>(depth[1], mask[1], depth[2], mask[2], depth[3], mask[3], out);
    (void)n_in; (void)out_size;
}

// round 9
// speedup vs baseline: 1.1552x; 1.0152x over previous
#include <cuda_runtime.h>
#include <math.h>

#define PI_F 3.14159265358979323846f
#define HPI_F 1.57079632679489662f

#define BB 8

// ---------- static scratch ----------
// L0 quad arrays, CHANNEL-MAJOR: word0 = R of 4 corners (y0x0,y0x1,y1x0,y1x1), word1 = G, word2 = B
__device__ uint4 g_q0[BB * 512 * 1024];   // 67MB
__device__ uint4 g_q1[BB * 512 * 1024];
// linear packed-RGB8 tgt mips per frame: L1@0 (1048576), L2@1048576 (262144), L3@1310720 (65536)
__device__ unsigned int g_c0[1376256];
__device__ unsigned int g_c1[1376256];
// channel-major quad mips (same offsets)
__device__ uint4 g_qm0[1376256];
__device__ uint4 g_qm1[1376256];
// ref planar fp32 mips ((b,c),h,w): L1@0, L2@3145728, L3@3932160
__device__ float g_refM[4128768];
__device__ float g_R[BB * 2 * 9];
__device__ float g_t[BB * 2 * 3];
// sincos tables: lon sizes 1024,512,256,128 @ offs 0,1024,1536,1792
//                lat sizes 512,256,128,64  @ offs 0,512,768,896
__device__ float2 g_lonT[1920];
__device__ float2 g_latT[960];
__device__ double g_acc[4];
__device__ int g_done;

#define TOTAL_LOSS_BLOCKS (16384 + 5376)

// ---------- init ----------
__global__ void bp_init(const float* __restrict__ pose) {
    int tid = threadIdx.x;
    if (tid < 4) g_acc[tid] = 0.0;
    if (tid == 4) g_done = 0;
    if (tid < BB * 2) {
        const float* p = pose + tid * 6;
        float rx = p[3], ry = p[4], rz = p[5];
        float th = sqrtf(rx * rx + ry * ry + rz * rz);
        float inv = 1.0f / fmaxf(th, 1e-8f);
        float kx = rx * inv, ky = ry * inv, kz = rz * inv;
        float s = sinf(th), c = cosf(th), ic = 1.0f - c;
        float* R = g_R + tid * 9;
        R[0] = c + ic * kx * kx;      R[1] = ic * kx * ky - s * kz; R[2] = ic * kx * kz + s * ky;
        R[3] = ic * ky * kx + s * kz; R[4] = c + ic * ky * ky;      R[5] = ic * ky * kz - s * kx;
        R[6] = ic * kz * kx - s * ky; R[7] = ic * kz * ky + s * kx; R[8] = c + ic * kz * kz;
        float* t = g_t + tid * 3;
        t[0] = p[0]; t[1] = p[1]; t[2] = p[2];
    }
    for (int i = tid; i < 1920; i += 256) {
        int off, w;
        if (i < 1024)      { off = 0;    w = 1024; }
        else if (i < 1536) { off = 1024; w = 512; }
        else if (i < 1792) { off = 1536; w = 256; }
        else               { off = 1792; w = 128; }
        int xi = i - off;
        float lon = ((xi + 0.5f) / (float)w * 2.0f - 1.0f) * PI_F;
        g_lonT[i] = make_float2(sinf(lon), cosf(lon));
    }
    for (int i = tid; i < 960; i += 256) {
        int off, h;
        if (i < 512)      { off = 0;   h = 512; }
        else if (i < 768) { off = 512; h = 256; }
        else if (i < 896) { off = 768; h = 128; }
        else              { off = 896; h = 64; }
        int yi = i - off;
        float lat = -((yi + 0.5f) / (float)h * 2.0f - 1.0f) * HPI_F;
        g_latT[i] = make_float2(sinf(lat), cosf(lat));
    }
}

// ---------- fast atan poly on [0,1], max err ~1e-5 rad ----------
__device__ __forceinline__ float atanp(float r) {
    float z = r * r;
    float p = -0.0117212f;
    p = fmaf(p, z, 0.05265332f);
    p = fmaf(p, z, -0.11643287f);
    p = fmaf(p, z, 0.19354346f);
    p = fmaf(p, z, -0.33262347f);
    p = fmaf(p, z, 0.99997726f);
    return r * p;
}

// ---------- project -> clamped sample coords ----------
__device__ __forceinline__ void project_eq(
    float px, float py, float pz, int h, int w, float& fx, float& fy)
{
    float ax = fabsf(px), az = fabsf(pz);
    float mn = fminf(ax, az), mx = fmaxf(ax, az);
    float t = atanp(__fdividef(mn, mx));
    t = (ax > az) ? (HPI_F - t) : t;
    t = (pz < 0.0f) ? (PI_F - t) : t;
    float lo = copysignf(t, px);
    float q = py * py;
    float s2 = fmaf(px, px, pz * pz);
    float mn2 = fminf(q, s2), mx2 = fmaxf(q, s2);
    float t2 = atanp(sqrtf(__fdividef(mn2, mx2)));
    t2 = (q > s2) ? (HPI_F - t2) : t2;
    float la = copysignf(t2, py);
    fx = (lo * (1.0f / PI_F) + 1.0f) * (0.5f * (float)(w - 1));
    fy = (la * (2.0f / PI_F) + 1.0f) * (0.5f * (float)(h - 1));
    fx = fminf(fmaxf(fx, 0.0f), (float)(w - 1));
    fy = fminf(fmaxf(fy, 0.0f), (float)(h - 1));
}

// ---------- quantize 3 fp32 -> packed RGB8 ----------
__device__ __forceinline__ unsigned int q8(float a, float b, float c) {
    unsigned int r = __float2uint_rn(__saturatef(a) * 255.0f);
    unsigned int g = __float2uint_rn(__saturatef(b) * 255.0f);
    unsigned int bl = __float2uint_rn(__saturatef(c) * 255.0f);
    return r | (g << 8) | (bl << 16);
}

// ---------- channel-major quad assembly from 4 corner RGB8 words ----------
__device__ __forceinline__ uint4 qassemble(unsigned a, unsigned b, unsigned c, unsigned d) {
    unsigned ab_r = __byte_perm(a, b, 0x0040), cd_r = __byte_perm(c, d, 0x0040);
    unsigned ab_g = __byte_perm(a, b, 0x0051), cd_g = __byte_perm(c, d, 0x0051);
    unsigned ab_b = __byte_perm(a, b, 0x0062), cd_b = __byte_perm(c, d, 0x0062);
    return make_uint4(__byte_perm(ab_r, cd_r, 0x5410),
                      __byte_perm(ab_g, cd_g, 0x5410),
                      __byte_perm(ab_b, cd_b, 0x5410), 0u);
}

// ---------- dp4a bilinear loss term (channel-major quad) ----------
__device__ __forceinline__ float quad_term(
    const uint4* __restrict__ Qarr, int b, int h, int w,
    float fx, float fy, float r0, float r1, float r2, float m)
{
    float x0f = floorf(fx), y0f = floorf(fy);
    int x0 = (int)x0f, y0 = (int)y0f;
    float wx1 = fx - x0f, wy1 = fy - y0f;
    float wx0 = 1.0f - wx1, wy0 = 1.0f - wy1;
    unsigned qa = __float2uint_rn(wx0 * wy0 * 255.0f);
    unsigned qc = __float2uint_rn(wx1 * wy0 * 255.0f);
    unsigned qb = __float2uint_rn(wx0 * wy1 * 255.0f);
    unsigned qd = __float2uint_rn(wx1 * wy1 * 255.0f);
    unsigned wq = qa | (qc << 8) | (qb << 16) | (qd << 24);
    unsigned sw = qa + qc + qb + qd;
    uint4 Q = __ldg(Qarr + (size_t)(b * h + y0) * w + x0);
    float inv = __fdividef(1.0f, (float)(sw * 255u));
    float w0 = (float)__dp4a(Q.x, wq, 0u) * inv;
    float w1 = (float)__dp4a(Q.y, wq, 0u) * inv;
    float w2 = (float)__dp4a(Q.z, wq, 0u) * inv;
    return m * (fabsf(r0 - w0) + fabsf(r1 - w1) + fabsf(r2 - w2));
}

// ---------- block reduce + done-count finalize ----------
__device__ __forceinline__ void loss_reduce_finalize(float acc, int accIdx, float* out) {
    #pragma unroll
    for (int o = 16; o > 0; o >>= 1) acc += __shfl_down_sync(0xffffffffu, acc, o);
    __shared__ float ws[8];
    int lane = threadIdx.x & 31, warp = threadIdx.x >> 5;
    if (lane == 0) ws[warp] = acc;
    __syncthreads();
    if (threadIdx.x == 0) {
        float s = 0.0f;
        #pragma unroll
        for (int i = 0; i < 8; i++) s += ws[i];
        atomicAdd(&g_acc[accIdx], (double)s);
        __threadfence();
        int done = atomicAdd(&g_done, 1);
        if (done == TOTAL_LOSS_BLOCKS - 1) {
            double l = g_acc[0] * (1.0 / 12582912.0)
                     + g_acc[1] * (1.0 / 3145728.0)
                     + g_acc[2] * (1.0 / 786432.0)
                     + g_acc[3] * (1.0 / 196608.0);
            out[0] = (float)l;
        }
    }
}

// ---------- DENSE (tgt only): L0 quads + RGB8 tgt mips ----------
// Block = 16x16 pixel tile; warp = 16x2 rows (lane = tx + 16*sub).
__global__ __launch_bounds__(256) void bp_dense(
    const float* __restrict__ tgt0, const float* __restrict__ tgt1)
{
    int tid = threadIdx.x;
    int lane = tid & 31, wid = tid >> 5;
    int blk = blockIdx.x;            // 16384 = 64 x 32 x 8
    int bx = blk & 63;
    int by = (blk >> 6) & 31;
    int b  = blk >> 11;
    int tx = lane & 15;
    int sub = lane >> 4;
    int lx = tx, ly = wid * 2 + sub;
    int x = bx * 16 + lx;
    int y = by * 16 + ly;

    const int hw = 512 * 1024;
    int p = y * 1024 + x;
    size_t base3 = (size_t)b * 3 * hw + p;

    float t00 = __ldg(tgt0 + base3), t01 = __ldg(tgt0 + base3 + hw), t02 = __ldg(tgt0 + base3 + 2 * hw);
    float t10 = __ldg(tgt1 + base3), t11 = __ldg(tgt1 + base3 + hw), t12 = __ldg(tgt1 + base3 + 2 * hw);

    __shared__ unsigned int sm0[17 * 17], sm1[17 * 17];
    sm0[ly * 17 + lx] = q8(t00, t01, t02);
    sm1[ly * 17 + lx] = q8(t10, t11, t12);
    // halo: right column (17) + bottom row (16)
    if (tid < 33) {
        int hlx, hly;
        if (tid < 17) { hlx = 16; hly = tid; }
        else          { hlx = tid - 17; hly = 16; }
        int gx = min(bx * 16 + hlx, 1023);
        int gy = min(by * 16 + hly, 511);
        size_t hb = (size_t)b * 3 * hw + gy * 1024 + gx;
        sm0[hly * 17 + hlx] = q8(__ldg(tgt0 + hb), __ldg(tgt0 + hb + hw), __ldg(tgt0 + hb + 2 * hw));
        sm1[hly * 17 + hlx] = q8(__ldg(tgt1 + hb), __ldg(tgt1 + hb + hw), __ldg(tgt1 + hb + 2 * hw));
    }

    // ---- L1 (2x2) via shuffles (fp32) ----
    #define RED4(v) { v += __shfl_xor_sync(0xffffffffu, v, 1); v += __shfl_xor_sync(0xffffffffu, v, 16); v *= 0.25f; }
    float c00 = t00, c01 = t01, c02 = t02;
    float c10 = t10, c11 = t11, c12 = t12;
    RED4(c00); RED4(c01); RED4(c02);
    RED4(c10); RED4(c11); RED4(c12);
    #undef RED4

    __shared__ float4 st0[64];
    __shared__ float4 st1[64];
    __shared__ float4 st0b[16];
    __shared__ float4 st1b[16];

    if (sub == 0 && (tx & 1) == 0) {
        int llx = tx >> 1, lly = wid;            // 8x8 local L1
        int x2 = bx * 8 + llx, y2 = by * 8 + lly;
        g_c0[(b * 256 + y2) * 512 + x2] = q8(c00, c01, c02);
        g_c1[(b * 256 + y2) * 512 + x2] = q8(c10, c11, c12);
        int si = lly * 8 + llx;
        st0[si] = make_float4(c00, c01, c02, 0.0f);
        st1[si] = make_float4(c10, c11, c12, 0.0f);
    }
    __syncthreads();

    // ---- L0 quad assembly + write (channel-major) ----
    {
        int si = ly * 17 + lx;
        g_q0[(size_t)(b * 512 + y) * 1024 + x] = qassemble(sm0[si], sm0[si + 1], sm0[si + 17], sm0[si + 18]);
        g_q1[(size_t)(b * 512 + y) * 1024 + x] = qassemble(sm1[si], sm1[si + 1], sm1[si + 17], sm1[si + 18]);
    }

    // ---- L2 (4x4 per block) ----
    if (tid < 16) {
        int lx2 = tid & 3, ly2 = tid >> 2;
        int i00 = (2 * ly2) * 8 + 2 * lx2;
        int i01 = i00 + 1, i10 = i00 + 8, i11 = i00 + 9;
        float q0x = 0.25f * (st0[i00].x + st0[i01].x + st0[i10].x + st0[i11].x);
        float q0y = 0.25f * (st0[i00].y + st0[i01].y + st0[i10].y + st0[i11].y);
        float q0z = 0.25f * (st0[i00].z + st0[i01].z + st0[i10].z + st0[i11].z);
        float q1x = 0.25f * (st1[i00].x + st1[i01].x + st1[i10].x + st1[i11].x);
        float q1y = 0.25f * (st1[i00].y + st1[i01].y + st1[i10].y + st1[i11].y);
        float q1z = 0.25f * (st1[i00].z + st1[i01].z + st1[i10].z + st1[i11].z);
        int x2g = bx * 4 + lx2, y2g = by * 4 + ly2;
        g_c0[1048576 + (b * 128 + y2g) * 256 + x2g] = q8(q0x, q0y, q0z);
        g_c1[1048576 + (b * 128 + y2g) * 256 + x2g] = q8(q1x, q1y, q1z);
        int si = ly2 * 4 + lx2;
        st0b[si] = make_float4(q0x, q0y, q0z, 0.0f);
        st1b[si] = make_float4(q1x, q1y, q1z, 0.0f);
    }
    __syncthreads();

    // ---- L3 (2x2 per block) ----
    if (tid < 4) {
        int lx3 = tid & 1, ly3 = tid >> 1;
        int i00 = (2 * ly3) * 4 + 2 * lx3;
        int i01 = i00 + 1, i10 = i00 + 4, i11 = i00 + 5;
        float q0x = 0.25f * (st0b[i00].x + st0b[i01].x + st0b[i10].x + st0b[i11].x);
        float q0y = 0.25f * (st0b[i00].y + st0b[i01].y + st0b[i10].y + st0b[i11].y);
        float q0z = 0.25f * (st0b[i00].z + st0b[i01].z + st0b[i10].z + st0b[i11].z);
        float q1x = 0.25f * (st1b[i00].x + st1b[i01].x + st1b[i10].x + st1b[i11].x);
        float q1y = 0.25f * (st1b[i00].y + st1b[i01].y + st1b[i10].y + st1b[i11].y);
        float q1z = 0.25f * (st1b[i00].z + st1b[i01].z + st1b[i10].z + st1b[i11].z);
        int x3g = bx * 2 + lx3, y3g = by * 2 + ly3;
        g_c0[1310720 + (b * 64 + y3g) * 128 + x3g] = q8(q0x, q0y, q0z);
        g_c1[1310720 + (b * 64 + y3g) * 128 + x3g] = q8(q1x, q1y, q1z);
    }
}

// ---------- pack mips into channel-major quads ----------
__global__ __launch_bounds__(256) void bp_pack() {
    int i = blockIdx.x * 256 + threadIdx.x;        // [0, 2752512)
    int f = (i >= 1376256);
    int j = i - f * 1376256;
    const unsigned int* src = f ? g_c1 : g_c0;
    uint4* dst = f ? g_qm1 : g_qm0;
    int off, w, h, lw, lh;
    if (j < 1048576)      { off = 0;       w = 512; h = 256; lw = 9; lh = 8; }
    else if (j < 1310720) { off = 1048576; w = 256; h = 128; lw = 8; lh = 7; }
    else                  { off = 1310720; w = 128; h = 64;  lw = 7; lh = 6; }
    int k = j - off;
    int x = k & (w - 1), y = (k >> lw) & (h - 1), b = k >> (lw + lh);
    int xq = min(x + 1, w - 1), yq = min(y + 1, h - 1);
    int row0 = off + (b * h + y) * w;
    int row1 = off + (b * h + yq) * w;
    dst[j] = qassemble(src[row0 + x], src[row0 + xq], src[row1 + x], src[row1 + xq]);
}

// ---------- loss level 0 + ref mip building ----------
__global__ __launch_bounds__(256) void bp_loss0(
    const float* __restrict__ ref, const float* __restrict__ depth,
    const float* __restrict__ mask, float* __restrict__ out)
{
    int tid = threadIdx.x;
    int lane = tid & 31, wid = tid >> 5;
    int blk = blockIdx.x;            // 16384 = 64 x 32 x 8
    int bx = blk & 63;
    int by = (blk >> 6) & 31;
    int b  = blk >> 11;
    int tx = lane & 15;
    int sub = lane >> 4;
    int x = bx * 16 + tx;
    int y = by * 16 + wid * 2 + sub;

    const int hw = 512 * 1024;
    int p = y * 1024 + x;
    size_t base3 = (size_t)b * 3 * hw + p;
    float r0 = __ldg(ref + base3), r1 = __ldg(ref + base3 + hw), r2 = __ldg(ref + base3 + 2 * hw);
    float d  = __ldg(depth + (size_t)b * hw + p);
    float m0 = __ldg(mask + (size_t)(b * 2) * hw + p);
    float m1 = __ldg(mask + (size_t)(b * 2 + 1) * hw + p);

    // ---- ref mips: L1 via shfl, L2/L3 via smem ----
    #define RED4(v) { v += __shfl_xor_sync(0xffffffffu, v, 1); v += __shfl_xor_sync(0xffffffffu, v, 16); v *= 0.25f; }
    float a0 = r0, a1 = r1, a2 = r2;
    RED4(a0); RED4(a1); RED4(a2);
    #undef RED4

    __shared__ float sref[3][64];
    __shared__ float sref2[3][16];
    if (sub == 0 && (tx & 1) == 0) {
        int llx = tx >> 1, lly = wid;
        int x2 = bx * 8 + llx, y2 = by * 8 + lly;
        size_t ro = (size_t)b * 393216 + y2 * 512 + x2;
        g_refM[ro] = a0; g_refM[ro + 131072] = a1; g_refM[ro + 262144] = a2;
        int si = lly * 8 + llx;
        sref[0][si] = a0; sref[1][si] = a1; sref[2][si] = a2;
    }
    __syncthreads();
    if (tid < 16) {
        int lx2 = tid & 3, ly2 = tid >> 2;
        int i00 = (2 * ly2) * 8 + 2 * lx2;
        int i01 = i00 + 1, i10 = i00 + 8, i11 = i00 + 9;
        float e0 = 0.25f * (sref[0][i00] + sref[0][i01] + sref[0][i10] + sref[0][i11]);
        float e1 = 0.25f * (sref[1][i00] + sref[1][i01] + sref[1][i10] + sref[1][i11]);
        float e2 = 0.25f * (sref[2][i00] + sref[2][i01] + sref[2][i10] + sref[2][i11]);
        int x2g = bx * 4 + lx2, y2g = by * 4 + ly2;
        size_t r2b = 3145728 + (size_t)b * 98304 + y2g * 256 + x2g;
        g_refM[r2b] = e0; g_refM[r2b + 32768] = e1; g_refM[r2b + 65536] = e2;
        int si = ly2 * 4 + lx2;
        sref2[0][si] = e0; sref2[1][si] = e1; sref2[2][si] = e2;
    }
    __syncthreads();
    if (tid < 4) {
        int lx3 = tid & 1, ly3 = tid >> 1;
        int i00 = (2 * ly3) * 4 + 2 * lx3;
        int i01 = i00 + 1, i10 = i00 + 4, i11 = i00 + 5;
        float e0 = 0.25f * (sref2[0][i00] + sref2[0][i01] + sref2[0][i10] + sref2[0][i11]);
        float e1 = 0.25f * (sref2[1][i00] + sref2[1][i01] + sref2[1][i10] + sref2[1][i11]);
        float e2 = 0.25f * (sref2[2][i00] + sref2[2][i01] + sref2[2][i10] + sref2[2][i11]);
        int x3g = bx * 2 + lx3, y3g = by * 2 + ly3;
        size_t r3b = 3932160 + (size_t)b * 24576 + y3g * 128 + x3g;
        g_refM[r3b] = e0; g_refM[r3b + 8192] = e1; g_refM[r3b + 16384] = e2;
    }

    // ---- loss ----
    float2 lc = g_lonT[x];
    float2 lt = g_latT[y];
    float xx = d * lt.y * lc.x;
    float yy = d * lt.x;
    float zz = d * lt.y * lc.y;
    float acc = 0.0f;
    #pragma unroll
    for (int n = 0; n < 2; n++) {
        const float* Rm = g_R + (b * 2 + n) * 9;
        const float* tv = g_t + (b * 2 + n) * 3;
        float px = __ldg(Rm+0) * xx + __ldg(Rm+1) * yy + __ldg(Rm+2) * zz + __ldg(tv+0);
        float py = __ldg(Rm+3) * xx + __ldg(Rm+4) * yy + __ldg(Rm+5) * zz + __ldg(tv+1);
        float pz = __ldg(Rm+6) * xx + __ldg(Rm+7) * yy + __ldg(Rm+8) * zz + __ldg(tv+2);
        float fx, fy;
        project_eq(px, py, pz, 512, 1024, fx, fy);
        acc += quad_term(n ? g_q1 : g_q0, b, 512, 1024, fx, fy, r0, r1, r2, n ? m1 : m0);
    }
    loss_reduce_finalize(acc, 0, out);
}

// ---------- loss levels 1..3 merged ----------
__global__ __launch_bounds__(256) void bp_loss123(
    const float* __restrict__ d1, const float* __restrict__ m1,
    const float* __restrict__ d2, const float* __restrict__ m2,
    const float* __restrict__ d3, const float* __restrict__ m3,
    float* __restrict__ out)
{
    int blk = blockIdx.x;
    const float *dep, *msk;
    int h, w, lw, lh, lonO, latO, accI, base;
    int qoff; size_t roff;
    if (blk < 4096)      { dep = d1; msk = m1; h = 256; w = 512; lw = 9; lh = 8; lonO = 1024; latO = 512; qoff = 0;       roff = 0;       accI = 1; base = 0; }
    else if (blk < 5120) { dep = d2; msk = m2; h = 128; w = 256; lw = 8; lh = 7; lonO = 1536; latO = 768; qoff = 1048576; roff = 3145728; accI = 2; base = 4096; }
    else                 { dep = d3; msk = m3; h = 64;  w = 128; lw = 7; lh = 6; lonO = 1792; latO = 896; qoff = 1310720; roff = 3932160; accI = 3; base = 5120; }
    int idx = (blk - base) * 256 + threadIdx.x;
    int x = idx & (w - 1), y = (idx >> lw) & (h - 1), b = idx >> (lw + lh);
    float2 lc = g_lonT[lonO + x];
    float2 lt = g_latT[latO + y];
    float d = __ldg(dep + idx);
    float xx = d * lt.y * lc.x;
    float yy = d * lt.x;
    float zz = d * lt.y * lc.y;
    int hw = h * w;
    int p = y * w + x;
    const float* rp = g_refM + roff + (size_t)b * 3 * hw + p;
    float r0 = rp[0], r1 = rp[hw], r2 = rp[2 * hw];
    float acc = 0.0f;
    #pragma unroll
    for (int n = 0; n < 2; n++) {
        const float* Rm = g_R + (b * 2 + n) * 9;
        const float* tv = g_t + (b * 2 + n) * 3;
        float px = __ldg(Rm+0) * xx + __ldg(Rm+1) * yy + __ldg(Rm+2) * zz + __ldg(tv+0);
        float py = __ldg(Rm+3) * xx + __ldg(Rm+4) * yy + __ldg(Rm+5) * zz + __ldg(tv+1);
        float pz = __ldg(Rm+6) * xx + __ldg(Rm+7) * yy + __ldg(Rm+8) * zz + __ldg(tv+2);
        float fx, fy;
        project_eq(px, py, pz, h, w, fx, fy);
        float m = __ldg(msk + (size_t)(b * 2 + n) * hw + p);
        acc += quad_term((n ? g_qm1 : g_qm0) + qoff, b, h, w, fx, fy, r0, r1, r2, m);
    }
    loss_reduce_finalize(acc, accI, out);
}

extern "C" void kernel_launch(void* const* d_in, const int* in_sizes, int n_in,
                              void* d_out, int out_size) {
    const float* depth[4];
    const float* mask[4];
    // Input-order detection: interleaved (dict order) vs grouped (signature order).
    if (in_sizes[2] == 8388608) {
        for (int i = 0; i < 4; i++) {
            depth[i] = (const float*)d_in[1 + 2 * i];
            mask[i]  = (const float*)d_in[2 + 2 * i];
        }
    } else {
        for (int i = 0; i < 4; i++) {
            depth[i] = (const float*)d_in[1 + i];
            mask[i]  = (const float*)d_in[5 + i];
        }
    }
    const float* ref_rgb = (const float*)d_in[0];
    const float* tgt0 = (const float*)d_in[9];
    const float* tgt1 = (const float*)d_in[10];
    const float* pose = (const float*)d_in[11];
    float* out = (float*)d_out;

    bp_init<<<1, 256>>>(pose);
    bp_dense<<<16384, 256>>>(tgt0, tgt1);
    bp_pack<<<10752, 256>>>();
    bp_loss0<<<16384, 256>>>(ref_rgb, depth[0], mask[0], out);
    bp_loss123<<<5376, 256>>>(depth[1], mask[1], depth[2], mask[2], depth[3], mask[3], out);
    (void)n_in; (void)out_size;
}

// round 10
// speedup vs baseline: 1.1687x; 1.0117x over previous
#include <cuda_runtime.h>
#include <math.h>

#define PI_F 3.14159265358979323846f
#define HPI_F 1.57079632679489662f

#define BB 8

// ---------- static scratch ----------
// L0 quad arrays, CHANNEL-MAJOR: word0 = R of 4 corners (y0x0,y0x1,y1x0,y1x1), word1 = G, word2 = B
__device__ uint4 g_q0[BB * 512 * 1024];   // 67MB
__device__ uint4 g_q1[BB * 512 * 1024];
// linear packed-RGB8 tgt mips per frame: L1@0 (1048576), L2@1048576 (262144), L3@1310720 (65536)
__device__ unsigned int g_c0[1376256];
__device__ unsigned int g_c1[1376256];
// channel-major quad mips (same offsets)
__device__ uint4 g_qm0[1376256];
__device__ uint4 g_qm1[1376256];
// ref planar fp32 mips, plane pp=b*3+c: L1@0 (stride 131072), L2@3145728 (32768), L3@3932160 (8192)
__device__ float g_refM[4128768];
// R|t packed rows: g_Rt[(b*2+n)*3 + r] = (R[r][0], R[r][1], R[r][2], t[r])
__device__ float4 g_Rt[BB * 2 * 3];
// sincos tables: lon sizes 1024,512,256,128 @ offs 0,1024,1536,1792
//                lat sizes 512,256,128,64  @ offs 0,512,768,896
__device__ float2 g_lonT[1920];
__device__ float2 g_latT[960];
__device__ double g_acc[4];
__device__ int g_done;

#define TOTAL_LOSS_BLOCKS (16384 + 5376)

// ---------- init ----------
__global__ void bp_init(const float* __restrict__ pose) {
    int tid = threadIdx.x;
    if (tid < 4) g_acc[tid] = 0.0;
    if (tid == 4) g_done = 0;
    if (tid < BB * 2) {
        const float* p = pose + tid * 6;
        float rx = p[3], ry = p[4], rz = p[5];
        float th = sqrtf(rx * rx + ry * ry + rz * rz);
        float inv = 1.0f / fmaxf(th, 1e-8f);
        float kx = rx * inv, ky = ry * inv, kz = rz * inv;
        float s = sinf(th), c = cosf(th), ic = 1.0f - c;
        g_Rt[tid * 3 + 0] = make_float4(c + ic * kx * kx,      ic * kx * ky - s * kz, ic * kx * kz + s * ky, p[0]);
        g_Rt[tid * 3 + 1] = make_float4(ic * ky * kx + s * kz, c + ic * ky * ky,      ic * ky * kz - s * kx, p[1]);
        g_Rt[tid * 3 + 2] = make_float4(ic * kz * kx - s * ky, ic * kz * ky + s * kx, c + ic * kz * kz,      p[2]);
    }
    for (int i = tid; i < 1920; i += 256) {
        int off, w;
        if (i < 1024)      { off = 0;    w = 1024; }
        else if (i < 1536) { off = 1024; w = 512; }
        else if (i < 1792) { off = 1536; w = 256; }
        else               { off = 1792; w = 128; }
        int xi = i - off;
        float lon = ((xi + 0.5f) / (float)w * 2.0f - 1.0f) * PI_F;
        g_lonT[i] = make_float2(sinf(lon), cosf(lon));
    }
    for (int i = tid; i < 960; i += 256) {
        int off, h;
        if (i < 512)      { off = 0;   h = 512; }
        else if (i < 768) { off = 512; h = 256; }
        else if (i < 896) { off = 768; h = 128; }
        else              { off = 896; h = 64; }
        int yi = i - off;
        float lat = -((yi + 0.5f) / (float)h * 2.0f - 1.0f) * HPI_F;
        g_latT[i] = make_float2(sinf(lat), cosf(lat));
    }
}

// ---------- fast atan poly on [0,1], max err ~1e-5 rad ----------
__device__ __forceinline__ float atanp(float r) {
    float z = r * r;
    float p = -0.0117212f;
    p = fmaf(p, z, 0.05265332f);
    p = fmaf(p, z, -0.11643287f);
    p = fmaf(p, z, 0.19354346f);
    p = fmaf(p, z, -0.33262347f);
    p = fmaf(p, z, 0.99997726f);
    return r * p;
}

// ---------- project -> clamped sample coords ----------
__device__ __forceinline__ void project_eq(
    float px, float py, float pz, int h, int w, float& fx, float& fy)
{
    float ax = fabsf(px), az = fabsf(pz);
    float mn = fminf(ax, az), mx = fmaxf(ax, az);
    float t = atanp(__fdividef(mn, mx));
    t = (ax > az) ? (HPI_F - t) : t;
    t = (pz < 0.0f) ? (PI_F - t) : t;
    float lo = copysignf(t, px);
    float q = py * py;
    float s2 = fmaf(px, px, pz * pz);
    float mn2 = fminf(q, s2), mx2 = fmaxf(q, s2);
    float t2 = atanp(sqrtf(__fdividef(mn2, mx2)));
    t2 = (q > s2) ? (HPI_F - t2) : t2;
    float la = copysignf(t2, py);
    fx = (lo * (1.0f / PI_F) + 1.0f) * (0.5f * (float)(w - 1));
    fy = (la * (2.0f / PI_F) + 1.0f) * (0.5f * (float)(h - 1));
    fx = fminf(fmaxf(fx, 0.0f), (float)(w - 1));
    fy = fminf(fmaxf(fy, 0.0f), (float)(h - 1));
}

// ---------- quantize 3 fp32 -> packed RGB8 ----------
__device__ __forceinline__ unsigned int q8(float a, float b, float c) {
    unsigned int r = __float2uint_rn(__saturatef(a) * 255.0f);
    unsigned int g = __float2uint_rn(__saturatef(b) * 255.0f);
    unsigned int bl = __float2uint_rn(__saturatef(c) * 255.0f);
    return r | (g << 8) | (bl << 16);
}

// ---------- channel-major quad assembly from 4 corner RGB8 words ----------
__device__ __forceinline__ uint4 qassemble(unsigned a, unsigned b, unsigned c, unsigned d) {
    unsigned ab_r = __byte_perm(a, b, 0x0040), cd_r = __byte_perm(c, d, 0x0040);
    unsigned ab_g = __byte_perm(a, b, 0x0051), cd_g = __byte_perm(c, d, 0x0051);
    unsigned ab_b = __byte_perm(a, b, 0x0062), cd_b = __byte_perm(c, d, 0x0062);
    return make_uint4(__byte_perm(ab_r, cd_r, 0x5410),
                      __byte_perm(ab_g, cd_g, 0x5410),
                      __byte_perm(ab_b, cd_b, 0x5410), 0u);
}

// ---------- dp4a bilinear loss term (channel-major quad, exact-sum weights) ----------
__device__ __forceinline__ float quad_term(
    const uint4* __restrict__ Qarr, int b, int h, int w,
    float fx, float fy, float r0, float r1, float r2, float m)
{
    float x0f = floorf(fx), y0f = floorf(fy);
    int x0 = (int)x0f, y0 = (int)y0f;
    float wx1 = fx - x0f, wy1 = fy - y0f;
    float wx0 = 1.0f - wx1, wy0 = 1.0f - wy1;
    unsigned qa = __float2uint_rn(wx0 * wy0 * 255.0f);
    unsigned qc = __float2uint_rn(wx1 * wy0 * 255.0f);
    unsigned qb = __float2uint_rn(wx0 * wy1 * 255.0f);
    int qdi = 255 - (int)(qa + qc + qb);
    unsigned qd = (unsigned)max(qdi, 0);
    unsigned wq = qa | (qc << 8) | (qb << 16) | (qd << 24);
    uint4 Q = __ldg(Qarr + (size_t)(b * h + y0) * w + x0);
    const float inv = 1.0f / 65025.0f;     // 1/(255*255)
    float w0 = (float)__dp4a(Q.x, wq, 0u) * inv;
    float w1 = (float)__dp4a(Q.y, wq, 0u) * inv;
    float w2 = (float)__dp4a(Q.z, wq, 0u) * inv;
    return m * (fabsf(r0 - w0) + fabsf(r1 - w1) + fabsf(r2 - w2));
}

// ---------- block reduce + done-count finalize ----------
__device__ __forceinline__ void loss_reduce_finalize(float acc, int accIdx, float* out) {
    #pragma unroll
    for (int o = 16; o > 0; o >>= 1) acc += __shfl_down_sync(0xffffffffu, acc, o);
    __shared__ float ws[8];
    int lane = threadIdx.x & 31, warp = threadIdx.x >> 5;
    if (lane == 0) ws[warp] = acc;
    __syncthreads();
    if (threadIdx.x == 0) {
        float s = 0.0f;
        #pragma unroll
        for (int i = 0; i < 8; i++) s += ws[i];
        atomicAdd(&g_acc[accIdx], (double)s);
        __threadfence();
        int done = atomicAdd(&g_done, 1);
        if (done == TOTAL_LOSS_BLOCKS - 1) {
            double l = g_acc[0] * (1.0 / 12582912.0)
                     + g_acc[1] * (1.0 / 3145728.0)
                     + g_acc[2] * (1.0 / 786432.0)
                     + g_acc[3] * (1.0 / 196608.0);
            out[0] = (float)l;
        }
    }
}

// ---------- DENSE (tgt only): L0 quads + RGB8 tgt mips ----------
__global__ __launch_bounds__(256) void bp_dense(
    const float* __restrict__ tgt0, const float* __restrict__ tgt1)
{
    int tid = threadIdx.x;
    int lane = tid & 31, wid = tid >> 5;
    int blk = blockIdx.x;            // 16384 = 64 x 32 x 8
    int bx = blk & 63;
    int by = (blk >> 6) & 31;
    int b  = blk >> 11;
    int tx = lane & 15;
    int sub = lane >> 4;
    int lx = tx, ly = wid * 2 + sub;
    int x = bx * 16 + lx;
    int y = by * 16 + ly;

    const int hw = 512 * 1024;
    int p = y * 1024 + x;
    size_t base3 = (size_t)b * 3 * hw + p;

    float t00 = __ldg(tgt0 + base3), t01 = __ldg(tgt0 + base3 + hw), t02 = __ldg(tgt0 + base3 + 2 * hw);
    float t10 = __ldg(tgt1 + base3), t11 = __ldg(tgt1 + base3 + hw), t12 = __ldg(tgt1 + base3 + 2 * hw);

    __shared__ unsigned int sm0[17 * 17], sm1[17 * 17];
    sm0[ly * 17 + lx] = q8(t00, t01, t02);
    sm1[ly * 17 + lx] = q8(t10, t11, t12);
    // halo: right column (17) + bottom row (16)
    if (tid < 33) {
        int hlx, hly;
        if (tid < 17) { hlx = 16; hly = tid; }
        else          { hlx = tid - 17; hly = 16; }
        int gx = min(bx * 16 + hlx, 1023);
        int gy = min(by * 16 + hly, 511);
        size_t hb = (size_t)b * 3 * hw + gy * 1024 + gx;
        sm0[hly * 17 + hlx] = q8(__ldg(tgt0 + hb), __ldg(tgt0 + hb + hw), __ldg(tgt0 + hb + 2 * hw));
        sm1[hly * 17 + hlx] = q8(__ldg(tgt1 + hb), __ldg(tgt1 + hb + hw), __ldg(tgt1 + hb + 2 * hw));
    }

    // ---- L1 (2x2) via shuffles (fp32) ----
    #define RED4(v) { v += __shfl_xor_sync(0xffffffffu, v, 1); v += __shfl_xor_sync(0xffffffffu, v, 16); v *= 0.25f; }
    float c00 = t00, c01 = t01, c02 = t02;
    float c10 = t10, c11 = t11, c12 = t12;
    RED4(c00); RED4(c01); RED4(c02);
    RED4(c10); RED4(c11); RED4(c12);
    #undef RED4

    __shared__ float4 st0[64];
    __shared__ float4 st1[64];
    __shared__ float4 st0b[16];
    __shared__ float4 st1b[16];

    if (sub == 0 && (tx & 1) == 0) {
        int llx = tx >> 1, lly = wid;            // 8x8 local L1
        int x2 = bx * 8 + llx, y2 = by * 8 + lly;
        g_c0[(b * 256 + y2) * 512 + x2] = q8(c00, c01, c02);
        g_c1[(b * 256 + y2) * 512 + x2] = q8(c10, c11, c12);
        int si = lly * 8 + llx;
        st0[si] = make_float4(c00, c01, c02, 0.0f);
        st1[si] = make_float4(c10, c11, c12, 0.0f);
    }
    __syncthreads();

    // ---- L0 quad assembly + write (channel-major) ----
    {
        int si = ly * 17 + lx;
        g_q0[(size_t)(b * 512 + y) * 1024 + x] = qassemble(sm0[si], sm0[si + 1], sm0[si + 17], sm0[si + 18]);
        g_q1[(size_t)(b * 512 + y) * 1024 + x] = qassemble(sm1[si], sm1[si + 1], sm1[si + 17], sm1[si + 18]);
    }

    // ---- L2 (4x4 per block) ----
    if (tid < 16) {
        int lx2 = tid & 3, ly2 = tid >> 2;
        int i00 = (2 * ly2) * 8 + 2 * lx2;
        int i01 = i00 + 1, i10 = i00 + 8, i11 = i00 + 9;
        float q0x = 0.25f * (st0[i00].x + st0[i01].x + st0[i10].x + st0[i11].x);
        float q0y = 0.25f * (st0[i00].y + st0[i01].y + st0[i10].y + st0[i11].y);
        float q0z = 0.25f * (st0[i00].z + st0[i01].z + st0[i10].z + st0[i11].z);
        float q1x = 0.25f * (st1[i00].x + st1[i01].x + st1[i10].x + st1[i11].x);
        float q1y = 0.25f * (st1[i00].y + st1[i01].y + st1[i10].y + st1[i11].y);
        float q1z = 0.25f * (st1[i00].z + st1[i01].z + st1[i10].z + st1[i11].z);
        int x2g = bx * 4 + lx2, y2g = by * 4 + ly2;
        g_c0[1048576 + (b * 128 + y2g) * 256 + x2g] = q8(q0x, q0y, q0z);
        g_c1[1048576 + (b * 128 + y2g) * 256 + x2g] = q8(q1x, q1y, q1z);
        int si = ly2 * 4 + lx2;
        st0b[si] = make_float4(q0x, q0y, q0z, 0.0f);
        st1b[si] = make_float4(q1x, q1y, q1z, 0.0f);
    }
    __syncthreads();

    // ---- L3 (2x2 per block) ----
    if (tid < 4) {
        int lx3 = tid & 1, ly3 = tid >> 1;
        int i00 = (2 * ly3) * 4 + 2 * lx3;
        int i01 = i00 + 1, i10 = i00 + 4, i11 = i00 + 5;
        float q0x = 0.25f * (st0b[i00].x + st0b[i01].x + st0b[i10].x + st0b[i11].x);
        float q0y = 0.25f * (st0b[i00].y + st0b[i01].y + st0b[i10].y + st0b[i11].y);
        float q0z = 0.25f * (st0b[i00].z + st0b[i01].z + st0b[i10].z + st0b[i11].z);
        float q1x = 0.25f * (st1b[i00].x + st1b[i01].x + st1b[i10].x + st1b[i11].x);
        float q1y = 0.25f * (st1b[i00].y + st1b[i01].y + st1b[i10].y + st1b[i11].y);
        float q1z = 0.25f * (st1b[i00].z + st1b[i01].z + st1b[i10].z + st1b[i11].z);
        int x3g = bx * 2 + lx3, y3g = by * 2 + ly3;
        g_c0[1310720 + (b * 64 + y3g) * 128 + x3g] = q8(q0x, q0y, q0z);
        g_c1[1310720 + (b * 64 + y3g) * 128 + x3g] = q8(q1x, q1y, q1z);
    }
}

// ---------- loss level 0 + ref L1 mip (sync-free) ----------
__global__ __launch_bounds__(256) void bp_loss0(
    const float* __restrict__ ref, const float* __restrict__ depth,
    const float* __restrict__ mask, float* __restrict__ out)
{
    int tid = threadIdx.x;
    int lane = tid & 31, wid = tid >> 5;
    int blk = blockIdx.x;            // 16384 = 64 x 32 x 8
    int bx = blk & 63;
    int by = (blk >> 6) & 31;
    int b  = blk >> 11;
    int tx = lane & 15;
    int sub = lane >> 4;
    int x = bx * 16 + tx;
    int y = by * 16 + wid * 2 + sub;

    const int hw = 512 * 1024;
    int p = y * 1024 + x;
    size_t base3 = (size_t)b * 3 * hw + p;
    float r0 = __ldg(ref + base3), r1 = __ldg(ref + base3 + hw), r2 = __ldg(ref + base3 + 2 * hw);
    float d  = __ldg(depth + (size_t)b * hw + p);
    float m0 = __ldg(mask + (size_t)(b * 2) * hw + p);
    float m1 = __ldg(mask + (size_t)(b * 2 + 1) * hw + p);

    // ---- ref L1 via shfl (no syncs) ----
    #define RED4(v) { v += __shfl_xor_sync(0xffffffffu, v, 1); v += __shfl_xor_sync(0xffffffffu, v, 16); v *= 0.25f; }
    float a0 = r0, a1 = r1, a2 = r2;
    RED4(a0); RED4(a1); RED4(a2);
    #undef RED4
    if (sub == 0 && (tx & 1) == 0) {
        int x2 = x >> 1, y2 = y >> 1;
        size_t ro = (size_t)(b * 3) * 131072 + y2 * 512 + x2;
        g_refM[ro] = a0; g_refM[ro + 131072] = a1; g_refM[ro + 262144] = a2;
    }

    // ---- loss ----
    float2 lc = g_lonT[x];
    float2 lt = g_latT[y];
    float xx = d * lt.y * lc.x;
    float yy = d * lt.x;
    float zz = d * lt.y * lc.y;
    float acc = 0.0f;
    #pragma unroll
    for (int n = 0; n < 2; n++) {
        const float4* Rt = g_Rt + (b * 2 + n) * 3;
        float4 A = __ldg(Rt), B = __ldg(Rt + 1), C = __ldg(Rt + 2);
        float px = A.x * xx + A.y * yy + A.z * zz + A.w;
        float py = B.x * xx + B.y * yy + B.z * zz + B.w;
        float pz = C.x * xx + C.y * yy + C.z * zz + C.w;
        float fx, fy;
        project_eq(px, py, pz, 512, 1024, fx, fy);
        acc += quad_term(n ? g_q1 : g_q0, b, 512, 1024, fx, fy, r0, r1, r2, n ? m1 : m0);
    }
    loss_reduce_finalize(acc, 0, out);
}

// ---------- pack: tgt mips -> quads, ref L1 -> L2/L3 ----------
// item ranges: [0, 2752512) tgt quad mips; [2752512, 3538944) ref L2; [3538944, 3735552) ref L3
__global__ __launch_bounds__(256) void bp_pack() {
    int i = blockIdx.x * 256 + threadIdx.x;
    if (i < 2752512) {
        int f = (i >= 1376256);
        int j = i - f * 1376256;
        const unsigned int* src = f ? g_c1 : g_c0;
        uint4* dst = f ? g_qm1 : g_qm0;
        int off, w, h, lw, lh;
        if (j < 1048576)      { off = 0;       w = 512; h = 256; lw = 9; lh = 8; }
        else if (j < 1310720) { off = 1048576; w = 256; h = 128; lw = 8; lh = 7; }
        else                  { off = 1310720; w = 128; h = 64;  lw = 7; lh = 6; }
        int k = j - off;
        int x = k & (w - 1), y = (k >> lw) & (h - 1), b = k >> (lw + lh);
        int xq = min(x + 1, w - 1), yq = min(y + 1, h - 1);
        int row0 = off + (b * h + y) * w;
        int row1 = off + (b * h + yq) * w;
        dst[j] = qassemble(src[row0 + x], src[row0 + xq], src[row1 + x], src[row1 + xq]);
    } else if (i < 3538944) {
        int k = i - 2752512;                      // ref L2: (pp, y, x) over 24 x 128 x 256
        int x = k & 255, y = (k >> 8) & 127, pp = k >> 15;
        const float* s = g_refM + (size_t)pp * 131072 + (2 * y) * 512 + 2 * x;
        g_refM[3145728 + (size_t)pp * 32768 + y * 256 + x] =
            0.25f * (s[0] + s[1] + s[512] + s[513]);
    } else if (i < 3735552) {
        int k = i - 3538944;                      // ref L3: (pp, y, x) over 24 x 64 x 128
        int x = k & 127, y = (k >> 7) & 63, pp = k >> 13;
        const float* s = g_refM + (size_t)pp * 131072 + (4 * y) * 512 + 4 * x;
        float sum = 0.0f;
        #pragma unroll
        for (int r = 0; r < 4; r++) {
            float4 q = *(const float4*)(s + r * 512);
            sum += q.x + q.y + q.z + q.w;
        }
        g_refM[3932160 + (size_t)pp * 8192 + y * 128 + x] = 0.0625f * sum;
    }
}

// ---------- loss levels 1..3 merged ----------
__global__ __launch_bounds__(256) void bp_loss123(
    const float* __restrict__ d1, const float* __restrict__ m1,
    const float* __restrict__ d2, const float* __restrict__ m2,
    const float* __restrict__ d3, const float* __restrict__ m3,
    float* __restrict__ out)
{
    int blk = blockIdx.x;
    const float *dep, *msk;
    int h, w, lw, lh, lonO, latO, accI, base;
    int qoff; size_t roff;
    if (blk < 4096)      { dep = d1; msk = m1; h = 256; w = 512; lw = 9; lh = 8; lonO = 1024; latO = 512; qoff = 0;       roff = 0;       accI = 1; base = 0; }
    else if (blk < 5120) { dep = d2; msk = m2; h = 128; w = 256; lw = 8; lh = 7; lonO = 1536; latO = 768; qoff = 1048576; roff = 3145728; accI = 2; base = 4096; }
    else                 { dep = d3; msk = m3; h = 64;  w = 128; lw = 7; lh = 6; lonO = 1792; latO = 896; qoff = 1310720; roff = 3932160; accI = 3; base = 5120; }
    int idx = (blk - base) * 256 + threadIdx.x;
    int x = idx & (w - 1), y = (idx >> lw) & (h - 1), b = idx >> (lw + lh);
    float2 lc = g_lonT[lonO + x];
    float2 lt = g_latT[latO + y];
    float d = __ldg(dep + idx);
    float xx = d * lt.y * lc.x;
    float yy = d * lt.x;
    float zz = d * lt.y * lc.y;
    int hw = h * w;
    int p = y * w + x;
    const float* rp = g_refM + roff + (size_t)(b * 3) * (roff == 0 ? 131072 : (roff == 3145728 ? 32768 : 8192)) + p;
    int pstride = (roff == 0 ? 131072 : (roff == 3145728 ? 32768 : 8192));
    float r0 = rp[0], r1 = rp[pstride], r2 = rp[2 * pstride];
    float acc = 0.0f;
    #pragma unroll
    for (int n = 0; n < 2; n++) {
        const float4* Rt = g_Rt + (b * 2 + n) * 3;
        float4 A = __ldg(Rt), B = __ldg(Rt + 1), C = __ldg(Rt + 2);
        float px = A.x * xx + A.y * yy + A.z * zz + A.w;
        float py = B.x * xx + B.y * yy + B.z * zz + B.w;
        float pz = C.x * xx + C.y * yy + C.z * zz + C.w;
        float fx, fy;
        project_eq(px, py, pz, h, w, fx, fy);
        float m = __ldg(msk + (size_t)(b * 2 + n) * hw + p);
        acc += quad_term((n ? g_qm1 : g_qm0) + qoff, b, h, w, fx, fy, r0, r1, r2, m);
    }
    loss_reduce_finalize(acc, accI, out);
}

extern "C" void kernel_launch(void* const* d_in, const int* in_sizes, int n_in,
                              void* d_out, int out_size) {
    const float* depth[4];
    const float* mask[4];
    // Input-order detection: interleaved (dict order) vs grouped (signature order).
    if (in_sizes[2] == 8388608) {
        for (int i = 0; i < 4; i++) {
            depth[i] = (const float*)d_in[1 + 2 * i];
            mask[i]  = (const float*)d_in[2 + 2 * i];
        }
    } else {
        for (int i = 0; i < 4; i++) {
            depth[i] = (const float*)d_in[1 + i];
            mask[i]  = (const float*)d_in[5 + i];
        }
    }
    const float* ref_rgb = (const float*)d_in[0];
    const float* tgt0 = (const float*)d_in[9];
    const float* tgt1 = (const float*)d_in[10];
    const float* pose = (const float*)d_in[11];
    float* out = (float*)d_out;

    bp_init<<<1, 256>>>(pose);
    bp_dense<<<16384, 256>>>(tgt0, tgt1);
    bp_loss0<<<16384, 256>>>(ref_rgb, depth[0], mask[0], out);
    bp_pack<<<14592, 256>>>();
    bp_loss123<<<5376, 256>>>(depth[1], mask[1], depth[2], mask[2], depth[3], mask[3], out);
    (void)n_in; (void)out_size;
}

// round 11
// speedup vs baseline: 1.2461x; 1.0662x over previous
#include <cuda_runtime.h>
#include <math.h>

#define PI_F 3.14159265358979323846f
#define HPI_F 1.57079632679489662f

#define BB 8

// ---------- static scratch ----------
// L0 quad arrays, CHANNEL-MAJOR: word0 = R of 4 corners (y0x0,y0x1,y1x0,y1x1), word1 = G, word2 = B
__device__ uint4 g_q0[BB * 512 * 1024];   // 67MB
__device__ uint4 g_q1[BB * 512 * 1024];
// linear packed-RGB8 tgt mips per frame: L1@0 (1048576), L2@1048576 (262144), L3@1310720 (65536)
__device__ unsigned int g_c0[1376256];
__device__ unsigned int g_c1[1376256];
// channel-major quad mips (same offsets)
__device__ uint4 g_qm0[1376256];
__device__ uint4 g_qm1[1376256];
// ref planar fp32 L1 mip, plane pp=b*3+c: stride 131072 (512x256)
__device__ __align__(16) float g_refM[3145728];
// R|t packed rows: g_Rt[(b*2+n)*3 + r] = (R[r][0], R[r][1], R[r][2], t[r])
__device__ float4 g_Rt[BB * 2 * 3];
// sincos tables: lon sizes 1024,512,256,128 @ offs 0,1024,1536,1792
//                lat sizes 512,256,128,64  @ offs 0,512,768,896
__device__ float2 g_lonT[1920];
__device__ float2 g_latT[960];
__device__ double g_acc[4];
__device__ int g_done;

#define TOTAL_LOSS_BLOCKS (16384 + 5376)

// ---------- fast atan poly on [0,1], max err ~1e-5 rad ----------
__device__ __forceinline__ float atanp(float r) {
    float z = r * r;
    float p = -0.0117212f;
    p = fmaf(p, z, 0.05265332f);
    p = fmaf(p, z, -0.11643287f);
    p = fmaf(p, z, 0.19354346f);
    p = fmaf(p, z, -0.33262347f);
    p = fmaf(p, z, 0.99997726f);
    return r * p;
}

// ---------- project -> clamped sample coords ----------
__device__ __forceinline__ void project_eq(
    float px, float py, float pz, int h, int w, float& fx, float& fy)
{
    float ax = fabsf(px), az = fabsf(pz);
    float mn = fminf(ax, az), mx = fmaxf(ax, az);
    float t = atanp(__fdividef(mn, mx));
    t = (ax > az) ? (HPI_F - t) : t;
    t = (pz < 0.0f) ? (PI_F - t) : t;
    float lo = copysignf(t, px);
    float q = py * py;
    float s2 = fmaf(px, px, pz * pz);
    float mn2 = fminf(q, s2), mx2 = fmaxf(q, s2);
    float t2 = atanp(sqrtf(__fdividef(mn2, mx2)));
    t2 = (q > s2) ? (HPI_F - t2) : t2;
    float la = copysignf(t2, py);
    fx = (lo * (1.0f / PI_F) + 1.0f) * (0.5f * (float)(w - 1));
    fy = (la * (2.0f / PI_F) + 1.0f) * (0.5f * (float)(h - 1));
    fx = fminf(fmaxf(fx, 0.0f), (float)(w - 1));
    fy = fminf(fmaxf(fy, 0.0f), (float)(h - 1));
}

// ---------- quantize 3 fp32 -> packed RGB8 ----------
__device__ __forceinline__ unsigned int q8(float a, float b, float c) {
    unsigned int r = __float2uint_rn(__saturatef(a) * 255.0f);
    unsigned int g = __float2uint_rn(__saturatef(b) * 255.0f);
    unsigned int bl = __float2uint_rn(__saturatef(c) * 255.0f);
    return r | (g << 8) | (bl << 16);
}

// ---------- channel-major quad assembly from 4 corner RGB8 words ----------
__device__ __forceinline__ uint4 qassemble(unsigned a, unsigned b, unsigned c, unsigned d) {
    unsigned ab_r = __byte_perm(a, b, 0x0040), cd_r = __byte_perm(c, d, 0x0040);
    unsigned ab_g = __byte_perm(a, b, 0x0051), cd_g = __byte_perm(c, d, 0x0051);
    unsigned ab_b = __byte_perm(a, b, 0x0062), cd_b = __byte_perm(c, d, 0x0062);
    return make_uint4(__byte_perm(ab_r, cd_r, 0x5410),
                      __byte_perm(ab_g, cd_g, 0x5410),
                      __byte_perm(ab_b, cd_b, 0x5410), 0u);
}

// ---------- dp4a bilinear loss term (channel-major quad, exact-sum weights) ----------
__device__ __forceinline__ float quad_term(
    const uint4* __restrict__ Qarr, int b, int h, int w,
    float fx, float fy, float r0, float r1, float r2, float m)
{
    float x0f = floorf(fx), y0f = floorf(fy);
    int x0 = (int)x0f, y0 = (int)y0f;
    float wx1 = fx - x0f, wy1 = fy - y0f;
    float wx0 = 1.0f - wx1, wy0 = 1.0f - wy1;
    unsigned qa = __float2uint_rn(wx0 * wy0 * 255.0f);
    unsigned qc = __float2uint_rn(wx1 * wy0 * 255.0f);
    unsigned qb = __float2uint_rn(wx0 * wy1 * 255.0f);
    int qdi = 255 - (int)(qa + qc + qb);
    unsigned qd = (unsigned)max(qdi, 0);
    unsigned wq = qa | (qc << 8) | (qb << 16) | (qd << 24);
    uint4 Q = __ldg(Qarr + (size_t)(b * h + y0) * w + x0);
    const float inv = 1.0f / 65025.0f;     // 1/(255*255)
    float w0 = (float)__dp4a(Q.x, wq, 0u) * inv;
    float w1 = (float)__dp4a(Q.y, wq, 0u) * inv;
    float w2 = (float)__dp4a(Q.z, wq, 0u) * inv;
    return m * (fabsf(r0 - w0) + fabsf(r1 - w1) + fabsf(r2 - w2));
}

// ---------- block reduce + done-count finalize ----------
__device__ __forceinline__ void loss_reduce_finalize(float acc, int accIdx, float* out) {
    #pragma unroll
    for (int o = 16; o > 0; o >>= 1) acc += __shfl_down_sync(0xffffffffu, acc, o);
    __shared__ float ws[8];
    int lane = threadIdx.x & 31, warp = threadIdx.x >> 5;
    if (lane == 0) ws[warp] = acc;
    __syncthreads();
    if (threadIdx.x == 0) {
        float s = 0.0f;
        #pragma unroll
        for (int i = 0; i < 8; i++) s += ws[i];
        atomicAdd(&g_acc[accIdx], (double)s);
        __threadfence();
        int done = atomicAdd(&g_done, 1);
        if (done == TOTAL_LOSS_BLOCKS - 1) {
            double l = g_acc[0] * (1.0 / 12582912.0)
                     + g_acc[1] * (1.0 / 3145728.0)
                     + g_acc[2] * (1.0 / 786432.0)
                     + g_acc[3] * (1.0 / 196608.0);
            out[0] = (float)l;
        }
    }
}

// ---------- DENSE (tgt only) + init in block 0 ----------
__global__ __launch_bounds__(256) void bp_dense(
    const float* __restrict__ tgt0, const float* __restrict__ tgt1,
    const float* __restrict__ pose)
{
    int tid = threadIdx.x;
    int blk = blockIdx.x;            // 16384 = 64 x 32 x 8

    // ---- init duties (block 0 only; outputs consumed by LATER kernels) ----
    if (blk == 0) {
        if (tid < 4) g_acc[tid] = 0.0;
        if (tid == 4) g_done = 0;
        if (tid < BB * 2) {
            const float* p = pose + tid * 6;
            float rx = p[3], ry = p[4], rz = p[5];
            float th = sqrtf(rx * rx + ry * ry + rz * rz);
            float inv = 1.0f / fmaxf(th, 1e-8f);
            float kx = rx * inv, ky = ry * inv, kz = rz * inv;
            float s = sinf(th), c = cosf(th), ic = 1.0f - c;
            g_Rt[tid * 3 + 0] = make_float4(c + ic * kx * kx,      ic * kx * ky - s * kz, ic * kx * kz + s * ky, p[0]);
            g_Rt[tid * 3 + 1] = make_float4(ic * ky * kx + s * kz, c + ic * ky * ky,      ic * ky * kz - s * kx, p[1]);
            g_Rt[tid * 3 + 2] = make_float4(ic * kz * kx - s * ky, ic * kz * ky + s * kx, c + ic * kz * kz,      p[2]);
        }
        for (int i = tid; i < 1920; i += 256) {
            int off, w;
            if (i < 1024)      { off = 0;    w = 1024; }
            else if (i < 1536) { off = 1024; w = 512; }
            else if (i < 1792) { off = 1536; w = 256; }
            else               { off = 1792; w = 128; }
            int xi = i - off;
            float lon = ((xi + 0.5f) / (float)w * 2.0f - 1.0f) * PI_F;
            g_lonT[i] = make_float2(sinf(lon), cosf(lon));
        }
        for (int i = tid; i < 960; i += 256) {
            int off, h;
            if (i < 512)      { off = 0;   h = 512; }
            else if (i < 768) { off = 512; h = 256; }
            else if (i < 896) { off = 768; h = 128; }
            else              { off = 896; h = 64; }
            int yi = i - off;
            float lat = -((yi + 0.5f) / (float)h * 2.0f - 1.0f) * HPI_F;
            g_latT[i] = make_float2(sinf(lat), cosf(lat));
        }
    }

    int lane = tid & 31, wid = tid >> 5;
    int bx = blk & 63;
    int by = (blk >> 6) & 31;
    int b  = blk >> 11;
    int tx = lane & 15;
    int sub = lane >> 4;
    int lx = tx, ly = wid * 2 + sub;
    int x = bx * 16 + lx;
    int y = by * 16 + ly;

    const int hw = 512 * 1024;
    int p = y * 1024 + x;
    size_t base3 = (size_t)b * 3 * hw + p;

    float t00 = __ldg(tgt0 + base3), t01 = __ldg(tgt0 + base3 + hw), t02 = __ldg(tgt0 + base3 + 2 * hw);
    float t10 = __ldg(tgt1 + base3), t11 = __ldg(tgt1 + base3 + hw), t12 = __ldg(tgt1 + base3 + 2 * hw);

    __shared__ unsigned int sm0[17 * 17], sm1[17 * 17];
    sm0[ly * 17 + lx] = q8(t00, t01, t02);
    sm1[ly * 17 + lx] = q8(t10, t11, t12);
    // halo: right column (17) + bottom row (16)
    if (tid < 33) {
        int hlx, hly;
        if (tid < 17) { hlx = 16; hly = tid; }
        else          { hlx = tid - 17; hly = 16; }
        int gx = min(bx * 16 + hlx, 1023);
        int gy = min(by * 16 + hly, 511);
        size_t hb = (size_t)b * 3 * hw + gy * 1024 + gx;
        sm0[hly * 17 + hlx] = q8(__ldg(tgt0 + hb), __ldg(tgt0 + hb + hw), __ldg(tgt0 + hb + 2 * hw));
        sm1[hly * 17 + hlx] = q8(__ldg(tgt1 + hb), __ldg(tgt1 + hb + hw), __ldg(tgt1 + hb + 2 * hw));
    }

    // ---- L1 (2x2) via shuffles (fp32) ----
    #define RED4(v) { v += __shfl_xor_sync(0xffffffffu, v, 1); v += __shfl_xor_sync(0xffffffffu, v, 16); v *= 0.25f; }
    float c00 = t00, c01 = t01, c02 = t02;
    float c10 = t10, c11 = t11, c12 = t12;
    RED4(c00); RED4(c01); RED4(c02);
    RED4(c10); RED4(c11); RED4(c12);
    #undef RED4

    __shared__ float4 st0[64];
    __shared__ float4 st1[64];
    __shared__ float4 st0b[16];
    __shared__ float4 st1b[16];

    if (sub == 0 && (tx & 1) == 0) {
        int llx = tx >> 1, lly = wid;            // 8x8 local L1
        int x2 = bx * 8 + llx, y2 = by * 8 + lly;
        g_c0[(b * 256 + y2) * 512 + x2] = q8(c00, c01, c02);
        g_c1[(b * 256 + y2) * 512 + x2] = q8(c10, c11, c12);
        int si = lly * 8 + llx;
        st0[si] = make_float4(c00, c01, c02, 0.0f);
        st1[si] = make_float4(c10, c11, c12, 0.0f);
    }
    __syncthreads();

    // ---- L0 quad assembly + write (channel-major) ----
    {
        int si = ly * 17 + lx;
        g_q0[(size_t)(b * 512 + y) * 1024 + x] = qassemble(sm0[si], sm0[si + 1], sm0[si + 17], sm0[si + 18]);
        g_q1[(size_t)(b * 512 + y) * 1024 + x] = qassemble(sm1[si], sm1[si + 1], sm1[si + 17], sm1[si + 18]);
    }

    // ---- L2 (4x4 per block) ----
    if (tid < 16) {
        int lx2 = tid & 3, ly2 = tid >> 2;
        int i00 = (2 * ly2) * 8 + 2 * lx2;
        int i01 = i00 + 1, i10 = i00 + 8, i11 = i00 + 9;
        float q0x = 0.25f * (st0[i00].x + st0[i01].x + st0[i10].x + st0[i11].x);
        float q0y = 0.25f * (st0[i00].y + st0[i01].y + st0[i10].y + st0[i11].y);
        float q0z = 0.25f * (st0[i00].z + st0[i01].z + st0[i10].z + st0[i11].z);
        float q1x = 0.25f * (st1[i00].x + st1[i01].x + st1[i10].x + st1[i11].x);
        float q1y = 0.25f * (st1[i00].y + st1[i01].y + st1[i10].y + st1[i11].y);
        float q1z = 0.25f * (st1[i00].z + st1[i01].z + st1[i10].z + st1[i11].z);
        int x2g = bx * 4 + lx2, y2g = by * 4 + ly2;
        g_c0[1048576 + (b * 128 + y2g) * 256 + x2g] = q8(q0x, q0y, q0z);
        g_c1[1048576 + (b * 128 + y2g) * 256 + x2g] = q8(q1x, q1y, q1z);
        int si = ly2 * 4 + lx2;
        st0b[si] = make_float4(q0x, q0y, q0z, 0.0f);
        st1b[si] = make_float4(q1x, q1y, q1z, 0.0f);
    }
    __syncthreads();

    // ---- L3 (2x2 per block) ----
    if (tid < 4) {
        int lx3 = tid & 1, ly3 = tid >> 1;
        int i00 = (2 * ly3) * 4 + 2 * lx3;
        int i01 = i00 + 1, i10 = i00 + 4, i11 = i00 + 5;
        float q0x = 0.25f * (st0b[i00].x + st0b[i01].x + st0b[i10].x + st0b[i11].x);
        float q0y = 0.25f * (st0b[i00].y + st0b[i01].y + st0b[i10].y + st0b[i11].y);
        float q0z = 0.25f * (st0b[i00].z + st0b[i01].z + st0b[i10].z + st0b[i11].z);
        float q1x = 0.25f * (st1b[i00].x + st1b[i01].x + st1b[i10].x + st1b[i11].x);
        float q1y = 0.25f * (st1b[i00].y + st1b[i01].y + st1b[i10].y + st1b[i11].y);
        float q1z = 0.25f * (st1b[i00].z + st1b[i01].z + st1b[i10].z + st1b[i11].z);
        int x3g = bx * 2 + lx3, y3g = by * 2 + ly3;
        g_c0[1310720 + (b * 64 + y3g) * 128 + x3g] = q8(q0x, q0y, q0z);
        g_c1[1310720 + (b * 64 + y3g) * 128 + x3g] = q8(q1x, q1y, q1z);
    }
}

// ---------- loss level 0 + ref L1 mip (blocks < 16384) ; tgt quad-mip packing (blocks >= 16384) ----------
__global__ __launch_bounds__(256) void bp_loss0(
    const float* __restrict__ ref, const float* __restrict__ depth,
    const float* __restrict__ mask, float* __restrict__ out)
{
    int tid = threadIdx.x;
    int blk = blockIdx.x;

    if (blk >= 16384) {
        // ---- tgt quad-mip packing (depends only on bp_dense output) ----
        int i = (blk - 16384) * 256 + tid;         // [0, 2752512)
        int f = (i >= 1376256);
        int j = i - f * 1376256;
        const unsigned int* src = f ? g_c1 : g_c0;
        uint4* dst = f ? g_qm1 : g_qm0;
        int off, w, h, lw, lh;
        if (j < 1048576)      { off = 0;       w = 512; h = 256; lw = 9; lh = 8; }
        else if (j < 1310720) { off = 1048576; w = 256; h = 128; lw = 8; lh = 7; }
        else                  { off = 1310720; w = 128; h = 64;  lw = 7; lh = 6; }
        int k = j - off;
        int x = k & (w - 1), y = (k >> lw) & (h - 1), b = k >> (lw + lh);
        int xq = min(x + 1, w - 1), yq = min(y + 1, h - 1);
        int row0 = off + (b * h + y) * w;
        int row1 = off + (b * h + yq) * w;
        dst[j] = qassemble(src[row0 + x], src[row0 + xq], src[row1 + x], src[row1 + xq]);
        return;
    }

    int lane = tid & 31, wid = tid >> 5;
    int bx = blk & 63;
    int by = (blk >> 6) & 31;
    int b  = blk >> 11;
    int tx = lane & 15;
    int sub = lane >> 4;
    int x = bx * 16 + tx;
    int y = by * 16 + wid * 2 + sub;

    const int hw = 512 * 1024;
    int p = y * 1024 + x;
    size_t base3 = (size_t)b * 3 * hw + p;
    float r0 = __ldg(ref + base3), r1 = __ldg(ref + base3 + hw), r2 = __ldg(ref + base3 + 2 * hw);
    float d  = __ldg(depth + (size_t)b * hw + p);
    float m0 = __ldg(mask + (size_t)(b * 2) * hw + p);
    float m1 = __ldg(mask + (size_t)(b * 2 + 1) * hw + p);

    // ---- ref L1 via shfl (no syncs) ----
    #define RED4(v) { v += __shfl_xor_sync(0xffffffffu, v, 1); v += __shfl_xor_sync(0xffffffffu, v, 16); v *= 0.25f; }
    float a0 = r0, a1 = r1, a2 = r2;
    RED4(a0); RED4(a1); RED4(a2);
    #undef RED4
    if (sub == 0 && (tx & 1) == 0) {
        int x2 = x >> 1, y2 = y >> 1;
        size_t ro = (size_t)(b * 3) * 131072 + y2 * 512 + x2;
        g_refM[ro] = a0; g_refM[ro + 131072] = a1; g_refM[ro + 262144] = a2;
    }

    // ---- loss ----
    float2 lc = g_lonT[x];
    float2 lt = g_latT[y];
    float xx = d * lt.y * lc.x;
    float yy = d * lt.x;
    float zz = d * lt.y * lc.y;
    float acc = 0.0f;
    #pragma unroll
    for (int n = 0; n < 2; n++) {
        const float4* Rt = g_Rt + (b * 2 + n) * 3;
        float4 A = __ldg(Rt), B = __ldg(Rt + 1), C = __ldg(Rt + 2);
        float px = A.x * xx + A.y * yy + A.z * zz + A.w;
        float py = B.x * xx + B.y * yy + B.z * zz + B.w;
        float pz = C.x * xx + C.y * yy + C.z * zz + C.w;
        float fx, fy;
        project_eq(px, py, pz, 512, 1024, fx, fy);
        acc += quad_term(n ? g_q1 : g_q0, b, 512, 1024, fx, fy, r0, r1, r2, n ? m1 : m0);
    }
    loss_reduce_finalize(acc, 0, out);
}

// ---------- loss levels 1..3 merged; ref L2/L3 computed inline from ref L1 ----------
__global__ __launch_bounds__(256) void bp_loss123(
    const float* __restrict__ d1, const float* __restrict__ m1,
    const float* __restrict__ d2, const float* __restrict__ m2,
    const float* __restrict__ d3, const float* __restrict__ m3,
    float* __restrict__ out)
{
    int blk = blockIdx.x;
    const float *dep, *msk;
    int h, w, lw, lh, lonO, latO, accI, base;
    int qoff;
    if (blk < 4096)      { dep = d1; msk = m1; h = 256; w = 512; lw = 9; lh = 8; lonO = 1024; latO = 512; qoff = 0;       accI = 1; base = 0; }
    else if (blk < 5120) { dep = d2; msk = m2; h = 128; w = 256; lw = 8; lh = 7; lonO = 1536; latO = 768; qoff = 1048576; accI = 2; base = 4096; }
    else                 { dep = d3; msk = m3; h = 64;  w = 128; lw = 7; lh = 6; lonO = 1792; latO = 896; qoff = 1310720; accI = 3; base = 5120; }
    int idx = (blk - base) * 256 + threadIdx.x;
    int x = idx & (w - 1), y = (idx >> lw) & (h - 1), b = idx >> (lw + lh);

    // ---- ref value from L1 mip ----
    float r0, r1, r2;
    {
        size_t pb = (size_t)(b * 3) * 131072;
        if (accI == 1) {
            size_t ro = pb + y * 512 + x;
            r0 = g_refM[ro]; r1 = g_refM[ro + 131072]; r2 = g_refM[ro + 262144];
        } else if (accI == 2) {
            size_t ro = pb + (2 * y) * 512 + 2 * x;
            float rr[3];
            #pragma unroll
            for (int c = 0; c < 3; c++) {
                float2 u0 = *(const float2*)(g_refM + ro + (size_t)c * 131072);
                float2 u1 = *(const float2*)(g_refM + ro + (size_t)c * 131072 + 512);
                rr[c] = 0.25f * (u0.x + u0.y + u1.x + u1.y);
            }
            r0 = rr[0]; r1 = rr[1]; r2 = rr[2];
        } else {
            size_t ro = pb + (4 * y) * 512 + 4 * x;
            float rr[3];
            #pragma unroll
            for (int c = 0; c < 3; c++) {
                float s = 0.0f;
                #pragma unroll
                for (int rrow = 0; rrow < 4; rrow++) {
                    float4 u = *(const float4*)(g_refM + ro + (size_t)c * 131072 + rrow * 512);
                    s += u.x + u.y + u.z + u.w;
                }
                rr[c] = 0.0625f * s;
            }
            r0 = rr[0]; r1 = rr[1]; r2 = rr[2];
        }
    }

    float2 lc = g_lonT[lonO + x];
    float2 lt = g_latT[latO + y];
    float d = __ldg(dep + idx);
    float xx = d * lt.y * lc.x;
    float yy = d * lt.x;
    float zz = d * lt.y * lc.y;
    int hw = h * w;
    int p = y * w + x;
    float acc = 0.0f;
    #pragma unroll
    for (int n = 0; n < 2; n++) {
        const float4* Rt = g_Rt + (b * 2 + n) * 3;
        float4 A = __ldg(Rt), B = __ldg(Rt + 1), C = __ldg(Rt + 2);
        float px = A.x * xx + A.y * yy + A.z * zz + A.w;
        float py = B.x * xx + B.y * yy + B.z * zz + B.w;
        float pz = C.x * xx + C.y * yy + C.z * zz + C.w;
        float fx, fy;
        project_eq(px, py, pz, h, w, fx, fy);
        float m = __ldg(msk + (size_t)(b * 2 + n) * hw + p);
        acc += quad_term((n ? g_qm1 : g_qm0) + qoff, b, h, w, fx, fy, r0, r1, r2, m);
    }
    loss_reduce_finalize(acc, accI, out);
}

extern "C" void kernel_launch(void* const* d_in, const int* in_sizes, int n_in,
                              void* d_out, int out_size) {
    const float* depth[4];
    const float* mask[4];
    // Input-order detection: interleaved (dict order) vs grouped (signature order).
    if (in_sizes[2] == 8388608) {
        for (int i = 0; i < 4; i++) {
            depth[i] = (const float*)d_in[1 + 2 * i];
            mask[i]  = (const float*)d_in[2 + 2 * i];
        }
    } else {
        for (int i = 0; i < 4; i++) {
            depth[i] = (const float*)d_in[1 + i];
            mask[i]  = (const float*)d_in[5 + i];
        }
    }
    const float* ref_rgb = (const float*)d_in[0];
    const float* tgt0 = (const float*)d_in[9];
    const float* tgt1 = (const float*)d_in[10];
    const float* pose = (const float*)d_in[11];
    float* out = (float*)d_out;

    bp_dense<<<16384, 256>>>(tgt0, tgt1, pose);
    bp_loss0<<<16384 + 10752, 256>>>(ref_rgb, depth[0], mask[0], out);
    bp_loss123<<<5376, 256>>>(depth[1], mask[1], depth[2], mask[2], depth[3], mask[3], out);
    (void)n_in; (void)out_size;
}

// round 12
// speedup vs baseline: 1.3010x; 1.0441x over previous
#include <cuda_runtime.h>
#include <math.h>

#define PI_F 3.14159265358979323846f
#define HPI_F 1.57079632679489662f

#define BB 8

// ---------- static scratch ----------
// L0 quad arrays, CHANNEL-MAJOR: word0 = R of 4 corners (y0x0,y0x1,y1x0,y1x1), word1 = G, word2 = B
__device__ uint4 g_q0[BB * 512 * 1024];   // 67MB
__device__ uint4 g_q1[BB * 512 * 1024];
// linear packed-RGB8 tgt mips per frame: L1@0 (1048576), L2@1048576 (262144), L3@1310720 (65536)
__device__ unsigned int g_c0[1376256];
__device__ unsigned int g_c1[1376256];
// channel-major quad mips (same offsets)
__device__ uint4 g_qm0[1376256];
__device__ uint4 g_qm1[1376256];
// ref planar fp32 L1 mip, plane pp=b*3+c: stride 131072 (512x256)
__device__ __align__(16) float g_refM[3145728];
// R|t packed rows: g_Rt[(b*2+n)*3 + r] = (R[r][0], R[r][1], R[r][2], t[r])
__device__ float4 g_Rt[BB * 2 * 3];
// sincos tables: lon sizes 1024,512,256,128 @ offs 0,1024,1536,1792
//                lat sizes 512,256,128,64  @ offs 0,512,768,896
__device__ float2 g_lonT[1920];
__device__ float2 g_latT[960];
__device__ double g_acc[4];
__device__ int g_done;

#define TOTAL_LOSS_BLOCKS (16384 + 5376)

// ---------- fast atan poly on [0,1], max err ~1e-5 rad ----------
__device__ __forceinline__ float atanp(float r) {
    float z = r * r;
    float p = -0.0117212f;
    p = fmaf(p, z, 0.05265332f);
    p = fmaf(p, z, -0.11643287f);
    p = fmaf(p, z, 0.19354346f);
    p = fmaf(p, z, -0.33262347f);
    p = fmaf(p, z, 0.99997726f);
    return r * p;
}

// ---------- project -> clamped sample coords ----------
__device__ __forceinline__ void project_eq(
    float px, float py, float pz, int h, int w, float& fx, float& fy)
{
    float ax = fabsf(px), az = fabsf(pz);
    float mn = fminf(ax, az), mx = fmaxf(ax, az);
    float t = atanp(__fdividef(mn, mx));
    t = (ax > az) ? (HPI_F - t) : t;
    t = (pz < 0.0f) ? (PI_F - t) : t;
    float lo = copysignf(t, px);
    float q = py * py;
    float s2 = fmaf(px, px, pz * pz);
    float mn2 = fminf(q, s2), mx2 = fmaxf(q, s2);
    float t2 = atanp(sqrtf(__fdividef(mn2, mx2)));
    t2 = (q > s2) ? (HPI_F - t2) : t2;
    float la = copysignf(t2, py);
    fx = (lo * (1.0f / PI_F) + 1.0f) * (0.5f * (float)(w - 1));
    fy = (la * (2.0f / PI_F) + 1.0f) * (0.5f * (float)(h - 1));
    fx = fminf(fmaxf(fx, 0.0f), (float)(w - 1));
    fy = fminf(fmaxf(fy, 0.0f), (float)(h - 1));
}

// ---------- quantize 3 fp32 -> packed RGB8 ----------
__device__ __forceinline__ unsigned int q8(float a, float b, float c) {
    unsigned int r = __float2uint_rn(__saturatef(a) * 255.0f);
    unsigned int g = __float2uint_rn(__saturatef(b) * 255.0f);
    unsigned int bl = __float2uint_rn(__saturatef(c) * 255.0f);
    return r | (g << 8) | (bl << 16);
}

// ---------- channel-major quad assembly from 4 corner RGB8 words ----------
__device__ __forceinline__ uint4 qassemble(unsigned a, unsigned b, unsigned c, unsigned d) {
    unsigned ab_r = __byte_perm(a, b, 0x0040), cd_r = __byte_perm(c, d, 0x0040);
    unsigned ab_g = __byte_perm(a, b, 0x0051), cd_g = __byte_perm(c, d, 0x0051);
    unsigned ab_b = __byte_perm(a, b, 0x0062), cd_b = __byte_perm(c, d, 0x0062);
    return make_uint4(__byte_perm(ab_r, cd_r, 0x5410),
                      __byte_perm(ab_g, cd_g, 0x5410),
                      __byte_perm(ab_b, cd_b, 0x5410), 0u);
}

// ---------- dp4a bilinear loss term (channel-major quad, exact-sum weights) ----------
__device__ __forceinline__ float quad_term(
    const uint4* __restrict__ Qarr, int b, int h, int w,
    float fx, float fy, float r0, float r1, float r2, float m)
{
    float x0f = floorf(fx), y0f = floorf(fy);
    int x0 = (int)x0f, y0 = (int)y0f;
    float wx1 = fx - x0f, wy1 = fy - y0f;
    float wx0 = 1.0f - wx1, wy0 = 1.0f - wy1;
    unsigned qa = __float2uint_rn(wx0 * wy0 * 255.0f);
    unsigned qc = __float2uint_rn(wx1 * wy0 * 255.0f);
    unsigned qb = __float2uint_rn(wx0 * wy1 * 255.0f);
    int qdi = 255 - (int)(qa + qc + qb);
    unsigned qd = (unsigned)max(qdi, 0);
    unsigned wq = qa | (qc << 8) | (qb << 16) | (qd << 24);
    uint4 Q = __ldg(Qarr + (size_t)(b * h + y0) * w + x0);
    const float inv = 1.0f / 65025.0f;     // 1/(255*255)
    float w0 = (float)__dp4a(Q.x, wq, 0u) * inv;
    float w1 = (float)__dp4a(Q.y, wq, 0u) * inv;
    float w2 = (float)__dp4a(Q.z, wq, 0u) * inv;
    return m * (fabsf(r0 - w0) + fabsf(r1 - w1) + fabsf(r2 - w2));
}

// ---------- block reduce + done-count finalize ----------
__device__ __forceinline__ void loss_reduce_finalize(float acc, int accIdx, float* out) {
    #pragma unroll
    for (int o = 16; o > 0; o >>= 1) acc += __shfl_down_sync(0xffffffffu, acc, o);
    __shared__ float ws[8];
    int lane = threadIdx.x & 31, warp = threadIdx.x >> 5;
    if (lane == 0) ws[warp] = acc;
    __syncthreads();
    if (threadIdx.x == 0) {
        float s = 0.0f;
        #pragma unroll
        for (int i = 0; i < 8; i++) s += ws[i];
        atomicAdd(&g_acc[accIdx], (double)s);
        __threadfence();
        int done = atomicAdd(&g_done, 1);
        if (done == TOTAL_LOSS_BLOCKS - 1) {
            double l = g_acc[0] * (1.0 / 12582912.0)
                     + g_acc[1] * (1.0 / 3145728.0)
                     + g_acc[2] * (1.0 / 786432.0)
                     + g_acc[3] * (1.0 / 196608.0);
            out[0] = (float)l;
        }
    }
}

// ---------- DENSE (tgt only), vectorized 4x: 32x32 tile per block ----------
__global__ __launch_bounds__(256) void bp_dense(
    const float* __restrict__ tgt0, const float* __restrict__ tgt1,
    const float* __restrict__ pose)
{
    int tid = threadIdx.x;
    int blk = blockIdx.x;            // 4096 = 32 x 16 x 8

    // ---- init duties (block 0 only; outputs consumed by LATER kernels) ----
    if (blk == 0) {
        if (tid < 4) g_acc[tid] = 0.0;
        if (tid == 4) g_done = 0;
        if (tid < BB * 2) {
            const float* p = pose + tid * 6;
            float rx = p[3], ry = p[4], rz = p[5];
            float th = sqrtf(rx * rx + ry * ry + rz * rz);
            float inv = 1.0f / fmaxf(th, 1e-8f);
            float kx = rx * inv, ky = ry * inv, kz = rz * inv;
            float s = sinf(th), c = cosf(th), ic = 1.0f - c;
            g_Rt[tid * 3 + 0] = make_float4(c + ic * kx * kx,      ic * kx * ky - s * kz, ic * kx * kz + s * ky, p[0]);
            g_Rt[tid * 3 + 1] = make_float4(ic * ky * kx + s * kz, c + ic * ky * ky,      ic * ky * kz - s * kx, p[1]);
            g_Rt[tid * 3 + 2] = make_float4(ic * kz * kx - s * ky, ic * kz * ky + s * kx, c + ic * kz * kz,      p[2]);
        }
        for (int i = tid; i < 1920; i += 256) {
            int off, w;
            if (i < 1024)      { off = 0;    w = 1024; }
            else if (i < 1536) { off = 1024; w = 512; }
            else if (i < 1792) { off = 1536; w = 256; }
            else               { off = 1792; w = 128; }
            int xi = i - off;
            float lon = ((xi + 0.5f) / (float)w * 2.0f - 1.0f) * PI_F;
            g_lonT[i] = make_float2(sinf(lon), cosf(lon));
        }
        for (int i = tid; i < 960; i += 256) {
            int off, h;
            if (i < 512)      { off = 0;   h = 512; }
            else if (i < 768) { off = 512; h = 256; }
            else if (i < 896) { off = 768; h = 128; }
            else              { off = 896; h = 64; }
            int yi = i - off;
            float lat = -((yi + 0.5f) / (float)h * 2.0f - 1.0f) * HPI_F;
            g_latT[i] = make_float2(sinf(lat), cosf(lat));
        }
    }

    int bx = blk & 31;
    int by = (blk >> 5) & 15;
    int b  = blk >> 9;
    int sx = tid & 7;                // 8 strips of 4 px
    int sy = tid >> 3;               // 32 rows
    int x0 = bx * 32 + sx * 4;
    int y  = by * 32 + sy;

    const int hw = 512 * 1024;
    size_t base3 = (size_t)b * 3 * hw + y * 1024 + x0;

    float4 a0 = *(const float4*)(tgt0 + base3);
    float4 a1 = *(const float4*)(tgt0 + base3 + hw);
    float4 a2 = *(const float4*)(tgt0 + base3 + 2 * hw);
    float4 b0 = *(const float4*)(tgt1 + base3);
    float4 b1 = *(const float4*)(tgt1 + base3 + hw);
    float4 b2 = *(const float4*)(tgt1 + base3 + 2 * hw);

    __shared__ unsigned smA[33 * 33], smB[33 * 33];
    {
        int si = sy * 33 + sx * 4;
        smA[si + 0] = q8(a0.x, a1.x, a2.x);
        smA[si + 1] = q8(a0.y, a1.y, a2.y);
        smA[si + 2] = q8(a0.z, a1.z, a2.z);
        smA[si + 3] = q8(a0.w, a1.w, a2.w);
        smB[si + 0] = q8(b0.x, b1.x, b2.x);
        smB[si + 1] = q8(b0.y, b1.y, b2.y);
        smB[si + 2] = q8(b0.z, b1.z, b2.z);
        smB[si + 3] = q8(b0.w, b1.w, b2.w);
    }
    // halo: right col (rows 0..31, lx=32) + bottom row (ly=32, cols 0..32) = 65 items/frame
    if (tid < 130) {
        int f = (tid >= 65);
        int i = tid - f * 65;
        int lxh, lyh;
        if (i < 32) { lxh = 32; lyh = i; }
        else        { lxh = i - 32; lyh = 32; }
        int gx = min(bx * 32 + lxh, 1023);
        int gy = min(by * 32 + lyh, 511);
        const float* src = f ? tgt1 : tgt0;
        size_t hb = (size_t)b * 3 * hw + gy * 1024 + gx;
        unsigned v = q8(__ldg(src + hb), __ldg(src + hb + hw), __ldg(src + hb + 2 * hw));
        (f ? smB : smA)[lyh * 33 + lxh] = v;
    }

    // ---- L1 (2x2): horizontal in-register + vertical shfl_xor(8) ----
    // h pairs per channel/frame
    float h0A0 = a0.x + a0.y, h1A0 = a0.z + a0.w;
    float h0A1 = a1.x + a1.y, h1A1 = a1.z + a1.w;
    float h0A2 = a2.x + a2.y, h1A2 = a2.z + a2.w;
    float h0B0 = b0.x + b0.y, h1B0 = b0.z + b0.w;
    float h0B1 = b1.x + b1.y, h1B1 = b1.z + b1.w;
    float h0B2 = b2.x + b2.y, h1B2 = b2.z + b2.w;
    #define Vred(v) v += __shfl_xor_sync(0xffffffffu, v, 8); v *= 0.25f;
    Vred(h0A0); Vred(h1A0); Vred(h0A1); Vred(h1A1); Vred(h0A2); Vred(h1A2);
    Vred(h0B0); Vred(h1B0); Vred(h0B1); Vred(h1B1); Vred(h0B2); Vred(h1B2);
    #undef Vred

    __shared__ float4 st0[256];      // L1 fp32, 16x16 per block
    __shared__ float4 st1[256];
    __shared__ float4 st0b[64];
    __shared__ float4 st1b[64];

    if ((sy & 1) == 0) {
        int lx1 = sx * 2, ly1 = sy >> 1;       // local L1 coords (16x16)
        int x2 = bx * 16 + lx1, y2 = by * 16 + ly1;
        int go = (b * 256 + y2) * 512 + x2;
        g_c0[go]     = q8(h0A0, h0A1, h0A2);
        g_c0[go + 1] = q8(h1A0, h1A1, h1A2);
        g_c1[go]     = q8(h0B0, h0B1, h0B2);
        g_c1[go + 1] = q8(h1B0, h1B1, h1B2);
        int si = ly1 * 16 + lx1;
        st0[si]     = make_float4(h0A0, h0A1, h0A2, 0.0f);
        st0[si + 1] = make_float4(h1A0, h1A1, h1A2, 0.0f);
        st1[si]     = make_float4(h0B0, h0B1, h0B2, 0.0f);
        st1[si + 1] = make_float4(h1B0, h1B1, h1B2, 0.0f);
    }
    __syncthreads();

    // ---- L0 quad assembly + write (channel-major) ----
    {
        int si = sy * 33 + sx * 4;
        unsigned rA0[5], rA1[5], rB0[5], rB1[5];
        #pragma unroll
        for (int i = 0; i < 5; i++) {
            rA0[i] = smA[si + i];      rA1[i] = smA[si + 33 + i];
            rB0[i] = smB[si + i];      rB1[i] = smB[si + 33 + i];
        }
        size_t go = (size_t)(b * 512 + y) * 1024 + x0;
        #pragma unroll
        for (int i = 0; i < 4; i++) {
            g_q0[go + i] = qassemble(rA0[i], rA0[i + 1], rA1[i], rA1[i + 1]);
            g_q1[go + i] = qassemble(rB0[i], rB0[i + 1], rB1[i], rB1[i + 1]);
        }
    }

    // ---- L2 (8x8 per block) ----
    if (tid < 64) {
        int lx2 = tid & 7, ly2 = tid >> 3;
        int i00 = (2 * ly2) * 16 + 2 * lx2;
        int i01 = i00 + 1, i10 = i00 + 16, i11 = i00 + 17;
        float q0x = 0.25f * (st0[i00].x + st0[i01].x + st0[i10].x + st0[i11].x);
        float q0y = 0.25f * (st0[i00].y + st0[i01].y + st0[i10].y + st0[i11].y);
        float q0z = 0.25f * (st0[i00].z + st0[i01].z + st0[i10].z + st0[i11].z);
        float q1x = 0.25f * (st1[i00].x + st1[i01].x + st1[i10].x + st1[i11].x);
        float q1y = 0.25f * (st1[i00].y + st1[i01].y + st1[i10].y + st1[i11].y);
        float q1z = 0.25f * (st1[i00].z + st1[i01].z + st1[i10].z + st1[i11].z);
        int x2g = bx * 8 + lx2, y2g = by * 8 + ly2;
        g_c0[1048576 + (b * 128 + y2g) * 256 + x2g] = q8(q0x, q0y, q0z);
        g_c1[1048576 + (b * 128 + y2g) * 256 + x2g] = q8(q1x, q1y, q1z);
        int si = ly2 * 8 + lx2;
        st0b[si] = make_float4(q0x, q0y, q0z, 0.0f);
        st1b[si] = make_float4(q1x, q1y, q1z, 0.0f);
    }
    __syncthreads();

    // ---- L3 (4x4 per block) ----
    if (tid < 16) {
        int lx3 = tid & 3, ly3 = tid >> 2;
        int i00 = (2 * ly3) * 8 + 2 * lx3;
        int i01 = i00 + 1, i10 = i00 + 8, i11 = i00 + 9;
        float q0x = 0.25f * (st0b[i00].x + st0b[i01].x + st0b[i10].x + st0b[i11].x);
        float q0y = 0.25f * (st0b[i00].y + st0b[i01].y + st0b[i10].y + st0b[i11].y);
        float q0z = 0.25f * (st0b[i00].z + st0b[i01].z + st0b[i10].z + st0b[i11].z);
        float q1x = 0.25f * (st1b[i00].x + st1b[i01].x + st1b[i10].x + st1b[i11].x);
        float q1y = 0.25f * (st1b[i00].y + st1b[i01].y + st1b[i10].y + st1b[i11].y);
        float q1z = 0.25f * (st1b[i00].z + st1b[i01].z + st1b[i10].z + st1b[i11].z);
        int x3g = bx * 4 + lx3, y3g = by * 4 + ly3;
        g_c0[1310720 + (b * 64 + y3g) * 128 + x3g] = q8(q0x, q0y, q0z);
        g_c1[1310720 + (b * 64 + y3g) * 128 + x3g] = q8(q1x, q1y, q1z);
    }
}

// ---------- loss level 0 + ref L1 mip (blocks < 16384) ; tgt quad-mip packing (blocks >= 16384) ----------
__global__ __launch_bounds__(256) void bp_loss0(
    const float* __restrict__ ref, const float* __restrict__ depth,
    const float* __restrict__ mask, float* __restrict__ out)
{
    int tid = threadIdx.x;
    int blk = blockIdx.x;

    if (blk >= 16384) {
        // ---- tgt quad-mip packing (depends only on bp_dense output) ----
        int i = (blk - 16384) * 256 + tid;         // [0, 2752512)
        int f = (i >= 1376256);
        int j = i - f * 1376256;
        const unsigned int* src = f ? g_c1 : g_c0;
        uint4* dst = f ? g_qm1 : g_qm0;
        int off, w, h, lw, lh;
        if (j < 1048576)      { off = 0;       w = 512; h = 256; lw = 9; lh = 8; }
        else if (j < 1310720) { off = 1048576; w = 256; h = 128; lw = 8; lh = 7; }
        else                  { off = 1310720; w = 128; h = 64;  lw = 7; lh = 6; }
        int k = j - off;
        int x = k & (w - 1), y = (k >> lw) & (h - 1), b = k >> (lw + lh);
        int xq = min(x + 1, w - 1), yq = min(y + 1, h - 1);
        int row0 = off + (b * h + y) * w;
        int row1 = off + (b * h + yq) * w;
        dst[j] = qassemble(src[row0 + x], src[row0 + xq], src[row1 + x], src[row1 + xq]);
        return;
    }

    int lane = tid & 31, wid = tid >> 5;
    int bx = blk & 63;
    int by = (blk >> 6) & 31;
    int b  = blk >> 11;
    int tx = lane & 15;
    int sub = lane >> 4;
    int x = bx * 16 + tx;
    int y = by * 16 + wid * 2 + sub;

    const int hw = 512 * 1024;
    int p = y * 1024 + x;
    size_t base3 = (size_t)b * 3 * hw + p;
    float r0 = __ldg(ref + base3), r1 = __ldg(ref + base3 + hw), r2 = __ldg(ref + base3 + 2 * hw);
    float d  = __ldg(depth + (size_t)b * hw + p);
    float m0 = __ldg(mask + (size_t)(b * 2) * hw + p);
    float m1 = __ldg(mask + (size_t)(b * 2 + 1) * hw + p);

    // ---- ref L1 via shfl (no syncs) ----
    #define RED4(v) { v += __shfl_xor_sync(0xffffffffu, v, 1); v += __shfl_xor_sync(0xffffffffu, v, 16); v *= 0.25f; }
    float a0 = r0, a1 = r1, a2 = r2;
    RED4(a0); RED4(a1); RED4(a2);
    #undef RED4
    if (sub == 0 && (tx & 1) == 0) {
        int x2 = x >> 1, y2 = y >> 1;
        size_t ro = (size_t)(b * 3) * 131072 + y2 * 512 + x2;
        g_refM[ro] = a0; g_refM[ro + 131072] = a1; g_refM[ro + 262144] = a2;
    }

    // ---- loss ----
    float2 lc = g_lonT[x];
    float2 lt = g_latT[y];
    float xx = d * lt.y * lc.x;
    float yy = d * lt.x;
    float zz = d * lt.y * lc.y;
    float acc = 0.0f;
    #pragma unroll
    for (int n = 0; n < 2; n++) {
        const float4* Rt = g_Rt + (b * 2 + n) * 3;
        float4 A = __ldg(Rt), B = __ldg(Rt + 1), C = __ldg(Rt + 2);
        float px = A.x * xx + A.y * yy + A.z * zz + A.w;
        float py = B.x * xx + B.y * yy + B.z * zz + B.w;
        float pz = C.x * xx + C.y * yy + C.z * zz + C.w;
        float fx, fy;
        project_eq(px, py, pz, 512, 1024, fx, fy);
        acc += quad_term(n ? g_q1 : g_q0, b, 512, 1024, fx, fy, r0, r1, r2, n ? m1 : m0);
    }
    loss_reduce_finalize(acc, 0, out);
}

// ---------- loss levels 1..3 merged; ref L2/L3 computed inline from ref L1 ----------
__global__ __launch_bounds__(256) void bp_loss123(
    const float* __restrict__ d1, const float* __restrict__ m1,
    const float* __restrict__ d2, const float* __restrict__ m2,
    const float* __restrict__ d3, const float* __restrict__ m3,
    float* __restrict__ out)
{
    int blk = blockIdx.x;
    const float *dep, *msk;
    int h, w, lw, lh, lonO, latO, accI, base;
    int qoff;
    if (blk < 4096)      { dep = d1; msk = m1; h = 256; w = 512; lw = 9; lh = 8; lonO = 1024; latO = 512; qoff = 0;       accI = 1; base = 0; }
    else if (blk < 5120) { dep = d2; msk = m2; h = 128; w = 256; lw = 8; lh = 7; lonO = 1536; latO = 768; qoff = 1048576; accI = 2; base = 4096; }
    else                 { dep = d3; msk = m3; h = 64;  w = 128; lw = 7; lh = 6; lonO = 1792; latO = 896; qoff = 1310720; accI = 3; base = 5120; }
    int idx = (blk - base) * 256 + threadIdx.x;
    int x = idx & (w - 1), y = (idx >> lw) & (h - 1), b = idx >> (lw + lh);

    // ---- ref value from L1 mip ----
    float r0, r1, r2;
    {
        size_t pb = (size_t)(b * 3) * 131072;
        if (accI == 1) {
            size_t ro = pb + y * 512 + x;
            r0 = g_refM[ro]; r1 = g_refM[ro + 131072]; r2 = g_refM[ro + 262144];
        } else if (accI == 2) {
            size_t ro = pb + (2 * y) * 512 + 2 * x;
            float rr[3];
            #pragma unroll
            for (int c = 0; c < 3; c++) {
                float2 u0 = *(const float2*)(g_refM + ro + (size_t)c * 131072);
                float2 u1 = *(const float2*)(g_refM + ro + (size_t)c * 131072 + 512);
                rr[c] = 0.25f * (u0.x + u0.y + u1.x + u1.y);
            }
            r0 = rr[0]; r1 = rr[1]; r2 = rr[2];
        } else {
            size_t ro = pb + (4 * y) * 512 + 4 * x;
            float rr[3];
            #pragma unroll
            for (int c = 0; c < 3; c++) {
                float s = 0.0f;
                #pragma unroll
                for (int rrow = 0; rrow < 4; rrow++) {
                    float4 u = *(const float4*)(g_refM + ro + (size_t)c * 131072 + rrow * 512);
                    s += u.x + u.y + u.z + u.w;
                }
                rr[c] = 0.0625f * s;
            }
            r0 = rr[0]; r1 = rr[1]; r2 = rr[2];
        }
    }

    float2 lc = g_lonT[lonO + x];
    float2 lt = g_latT[latO + y];
    float d = __ldg(dep + idx);
    float xx = d * lt.y * lc.x;
    float yy = d * lt.x;
    float zz = d * lt.y * lc.y;
    int hw = h * w;
    int p = y * w + x;
    float acc = 0.0f;
    #pragma unroll
    for (int n = 0; n < 2; n++) {
        const float4* Rt = g_Rt + (b * 2 + n) * 3;
        float4 A = __ldg(Rt), B = __ldg(Rt + 1), C = __ldg(Rt + 2);
        float px = A.x * xx + A.y * yy + A.z * zz + A.w;
        float py = B.x * xx + B.y * yy + B.z * zz + B.w;
        float pz = C.x * xx + C.y * yy + C.z * zz + C.w;
        float fx, fy;
        project_eq(px, py, pz, h, w, fx, fy);
        float m = __ldg(msk + (size_t)(b * 2 + n) * hw + p);
        acc += quad_term((n ? g_qm1 : g_qm0) + qoff, b, h, w, fx, fy, r0, r1, r2, m);
    }
    loss_reduce_finalize(acc, accI, out);
}

extern "C" void kernel_launch(void* const* d_in, const int* in_sizes, int n_in,
                              void* d_out, int out_size) {
    const float* depth[4];
    const float* mask[4];
    // Input-order detection: interleaved (dict order) vs grouped (signature order).
    if (in_sizes[2] == 8388608) {
        for (int i = 0; i < 4; i++) {
            depth[i] = (const float*)d_in[1 + 2 * i];
            mask[i]  = (const float*)d_in[2 + 2 * i];
        }
    } else {
        for (int i = 0; i < 4; i++) {
            depth[i] = (const float*)d_in[1 + i];
            mask[i]  = (const float*)d_in[5 + i];
        }
    }
    const float* ref_rgb = (const float*)d_in[0];
    const float* tgt0 = (const float*)d_in[9];
    const float* tgt1 = (const float*)d_in[10];
    const float* pose = (const float*)d_in[11];
    float* out = (float*)d_out;

    bp_dense<<<4096, 256>>>(tgt0, tgt1, pose);
    bp_loss0<<<16384 + 10752, 256>>>(ref_rgb, depth[0], mask[0], out);
    bp_loss123<<<5376, 256>>>(depth[1], mask[1], depth[2], mask[2], depth[3], mask[3], out);
    (void)n_in; (void)out_size;
}